// round 1
// baseline (speedup 1.0000x reference)
#include <cuda_runtime.h>
#include <math.h>

#define BB 16
#define SS 1024
#define EE 256
#define HH 8
#define DH 32
#define MROWS (BB*SS)   // 16384

// ---------------- scratch (static device arrays; no allocation allowed) ----
__device__ float g_ln   [MROWS*EE];
__device__ float g_q    [MROWS*EE];
__device__ float g_k    [MROWS*EE];
__device__ float g_v    [MROWS*EE];
__device__ float g_gate0[MROWS*EE];
__device__ float g_o    [MROWS*EE];
__device__ float g_gate1[MROWS*EE];
__device__ float g_mlp  [MROWS*EE];

// ---------------- block reduction helper (blockDim.x == 256) ---------------
__device__ __forceinline__ float block_sum256(float v, float* sh) {
    #pragma unroll
    for (int o = 16; o > 0; o >>= 1) v += __shfl_xor_sync(0xffffffffu, v, o);
    int w = threadIdx.x >> 5;
    if ((threadIdx.x & 31) == 0) sh[w] = v;
    __syncthreads();
    if (w == 0) {
        float s = (threadIdx.x < 8) ? sh[threadIdx.x] : 0.f;
        #pragma unroll
        for (int o = 4; o > 0; o >>= 1) s += __shfl_xor_sync(0xffffffffu, s, o);
        if (threadIdx.x == 0) sh[0] = s;
    }
    __syncthreads();
    float r = sh[0];
    __syncthreads();
    return r;
}

// ---------------- layernorm of input ---------------------------------------
__global__ __launch_bounds__(256) void ln_kernel(
    const float* __restrict__ x, const float* __restrict__ g,
    const float* __restrict__ b, float* __restrict__ out)
{
    __shared__ float sh[8];
    int row = blockIdx.x;
    int e   = threadIdx.x;
    float v = x[row*EE + e];
    float mean = block_sum256(v, sh) * (1.f/EE);
    float d = v - mean;
    float var = block_sum256(d*d, sh) * (1.f/EE);
    float rstd = rsqrtf(var + 1e-5f);
    out[row*EE + e] = d * rstd * g[e] + b[e];
}

// ---------------- final: out = gate1 * LN(mlp) + gate1 ---------------------
__global__ __launch_bounds__(256) void final_kernel(
    const float* __restrict__ mlp, const float* __restrict__ gate1,
    const float* __restrict__ g, const float* __restrict__ b,
    float* __restrict__ out)
{
    __shared__ float sh[8];
    int row = blockIdx.x;
    int e   = threadIdx.x;
    float v = mlp[row*EE + e];
    float mean = block_sum256(v, sh) * (1.f/EE);
    float d = v - mean;
    float var = block_sum256(d*d, sh) * (1.f/EE);
    float rstd = rsqrtf(var + 1e-5f);
    float lnm = d * rstd * g[e] + b[e];
    float g1 = gate1[row*EE + e];
    out[row*EE + e] = g1 * lnm + g1;
}

// ---------------- tiled SGEMM: C[M=16384,256] = A[M,256] @ W[256,256] ------
// epilogue: 0 = +bias ; 1 = sigmoid(+bias) ; 2 = aux1*( +bias ) + aux2
__global__ __launch_bounds__(256) void gemm_kernel(
    const float* __restrict__ A, const float* __restrict__ W,
    const float* __restrict__ bias, float* __restrict__ C,
    const float* __restrict__ aux1, const float* __restrict__ aux2,
    int epilogue)
{
    __shared__ float As[64][17];
    __shared__ float Bs[16][68];

    int tid = threadIdx.x;
    int tx = tid & 15;          // 0..15 -> col group
    int ty = tid >> 4;          // 0..15 -> row group
    int m0 = blockIdx.y * 64;
    int n0 = blockIdx.x * 64;

    float acc[4][4];
    #pragma unroll
    for (int i = 0; i < 4; i++)
        #pragma unroll
        for (int j = 0; j < 4; j++) acc[i][j] = 0.f;

    for (int k0 = 0; k0 < EE; k0 += 16) {
        // load A tile 64x16 (float4 each thread)
        {
            int i = tid * 4;
            int r = i >> 4, c = i & 15;
            float4 a = *(const float4*)&A[(size_t)(m0 + r)*EE + k0 + c];
            As[r][c+0] = a.x; As[r][c+1] = a.y; As[r][c+2] = a.z; As[r][c+3] = a.w;
        }
        // load B tile 16x64 (float4 each thread)
        {
            int i = tid * 4;
            int r = i >> 6, c = i & 63;
            float4 w = *(const float4*)&W[(size_t)(k0 + r)*EE + n0 + c];
            Bs[r][c+0] = w.x; Bs[r][c+1] = w.y; Bs[r][c+2] = w.z; Bs[r][c+3] = w.w;
        }
        __syncthreads();

        #pragma unroll
        for (int kk = 0; kk < 16; kk++) {
            float a0 = As[ty*4+0][kk];
            float a1 = As[ty*4+1][kk];
            float a2 = As[ty*4+2][kk];
            float a3 = As[ty*4+3][kk];
            float4 b4 = *(const float4*)&Bs[kk][tx*4];
            float br[4] = {b4.x, b4.y, b4.z, b4.w};
            #pragma unroll
            for (int j = 0; j < 4; j++) {
                acc[0][j] = fmaf(a0, br[j], acc[0][j]);
                acc[1][j] = fmaf(a1, br[j], acc[1][j]);
                acc[2][j] = fmaf(a2, br[j], acc[2][j]);
                acc[3][j] = fmaf(a3, br[j], acc[3][j]);
            }
        }
        __syncthreads();
    }

    #pragma unroll
    for (int i = 0; i < 4; i++) {
        int row = m0 + ty*4 + i;
        #pragma unroll
        for (int j = 0; j < 4; j++) {
            int col = n0 + tx*4 + j;
            float v = acc[i][j] + bias[col];
            if (epilogue == 1) {
                v = 1.f / (1.f + __expf(-v));
            } else if (epilogue == 2) {
                size_t idx = (size_t)row*EE + col;
                v = aux1[idx] * v + aux2[idx];
            }
            C[(size_t)row*EE + col] = v;
        }
    }
}

// ---------------- flash-style attention ------------------------------------
// grid: (B*H, S/TQ), block: TQ threads. one thread = one query row.
#define TQ 128
#define TK 32
__global__ __launch_bounds__(TQ) void attn_kernel(
    const float* __restrict__ q, const float* __restrict__ k,
    const float* __restrict__ v, const float* __restrict__ rbias,
    float* __restrict__ o)
{
    __shared__ float Ks[TK*DH];           // 4 KB
    __shared__ float Vs[TK*DH];           // 4 KB
    __shared__ float Bsh[TQ*(TK+1)];      // 16.5 KB, pad avoids 32-way conflicts

    int bh = blockIdx.x;                  // 0..127
    int b  = bh >> 3;
    int h  = bh & 7;
    int q0 = blockIdx.y * TQ;
    int t  = threadIdx.x;
    int qrow = b*SS + q0 + t;

    const float inv_sqrt_dh = 0.17677669529663687f;  // 1/sqrt(32)

    float qr[DH];
    #pragma unroll
    for (int d = 0; d < DH; d++)
        qr[d] = q[(size_t)qrow*EE + h*DH + d] * inv_sqrt_dh;

    float m = -1e30f, l = 0.f;
    float acc[DH];
    #pragma unroll
    for (int d = 0; d < DH; d++) acc[d] = 0.f;

    for (int k0 = 0; k0 < SS; k0 += TK) {
        // load K/V tiles: TK*DH = 1024 floats each
        for (int i = t; i < TK*DH; i += TQ) {
            int kr = i >> 5, d = i & 31;
            size_t grow = (size_t)(b*SS + k0 + kr)*EE + h*DH + d;
            Ks[i] = k[grow];
            Vs[i] = v[grow];
        }
        // load bias tile [TQ][TK] coalesced
        for (int i = t; i < TQ*TK; i += TQ) {
            int r = i >> 5, c = i & 31;
            Bsh[r*(TK+1) + c] = rbias[(size_t)(q0 + r)*SS + k0 + c];
        }
        __syncthreads();

        #pragma unroll 4
        for (int j = 0; j < TK; j++) {
            float s = Bsh[t*(TK+1) + j];
            #pragma unroll
            for (int d = 0; d < DH; d++)
                s = fmaf(qr[d], Ks[j*DH + d], s);
            if (s > m) {
                float sc = __expf(m - s);
                l *= sc;
                #pragma unroll
                for (int d = 0; d < DH; d++) acc[d] *= sc;
                m = s;
            }
            float p = __expf(s - m);
            l += p;
            #pragma unroll
            for (int d = 0; d < DH; d++)
                acc[d] = fmaf(p, Vs[j*DH + d], acc[d]);
        }
        __syncthreads();
    }

    float inv = 1.f / l;
    #pragma unroll
    for (int d = 0; d < DH; d++)
        o[(size_t)qrow*EE + h*DH + d] = acc[d] * inv;
}

// ---------------- launch ----------------------------------------------------
extern "C" void kernel_launch(void* const* d_in, const int* in_sizes, int n_in,
                              void* d_out, int out_size)
{
    const float* Matrix = (const float*)d_in[0];
    const float* ln_g   = (const float*)d_in[1];
    const float* ln_b   = (const float*)d_in[2];
    const float* Wq     = (const float*)d_in[3];
    const float* bq     = (const float*)d_in[4];
    const float* Wk     = (const float*)d_in[5];
    const float* bk     = (const float*)d_in[6];
    const float* Wv     = (const float*)d_in[7];
    const float* bv     = (const float*)d_in[8];
    const float* Wo     = (const float*)d_in[9];
    const float* bo     = (const float*)d_in[10];
    const float* rel    = (const float*)d_in[11];
    const float* gW     = (const float*)d_in[12];
    const float* gb     = (const float*)d_in[13];
    const float* mW     = (const float*)d_in[14];
    const float* mb     = (const float*)d_in[15];
    float* out = (float*)d_out;

    float *ln, *qb, *kb, *vb, *gate0, *ob, *gate1, *mlp;
    cudaGetSymbolAddress((void**)&ln,    g_ln);
    cudaGetSymbolAddress((void**)&qb,    g_q);
    cudaGetSymbolAddress((void**)&kb,    g_k);
    cudaGetSymbolAddress((void**)&vb,    g_v);
    cudaGetSymbolAddress((void**)&gate0, g_gate0);
    cudaGetSymbolAddress((void**)&ob,    g_o);
    cudaGetSymbolAddress((void**)&gate1, g_gate1);
    cudaGetSymbolAddress((void**)&mlp,   g_mlp);

    dim3 ggrid(EE/64, MROWS/64);   // (4, 256)

    // 1. ln = LayerNorm(Matrix)
    ln_kernel<<<MROWS, 256>>>(Matrix, ln_g, ln_b, ln);

    // 2. q/k/v projections (from ln), gate0 = sigmoid(Matrix@gW+gb)
    gemm_kernel<<<ggrid, 256>>>(ln, Wq, bq, qb, nullptr, nullptr, 0);
    gemm_kernel<<<ggrid, 256>>>(ln, Wk, bk, kb, nullptr, nullptr, 0);
    gemm_kernel<<<ggrid, 256>>>(ln, Wv, bv, vb, nullptr, nullptr, 0);
    gemm_kernel<<<ggrid, 256>>>(Matrix, gW, gb, gate0, nullptr, nullptr, 1);

    // 3. attention -> o
    attn_kernel<<<dim3(BB*HH, SS/TQ), TQ>>>(qb, kb, vb, rel, ob);

    // 4. rmha = o@Wo+bo ; fused: gate1 = gate0*rmha + Matrix
    gemm_kernel<<<ggrid, 256>>>(ob, Wo, bo, gate1, gate0, Matrix, 2);

    // 5. mlp = sigmoid(gate1@mW+mb)
    gemm_kernel<<<ggrid, 256>>>(gate1, mW, mb, mlp, nullptr, nullptr, 1);

    // 6. final = gate1*LN(mlp) + gate1
    final_kernel<<<MROWS, 256>>>(mlp, gate1, ln_g, ln_b, out);
}

// round 2
// speedup vs baseline: 1.4895x; 1.4895x over previous
#include <cuda_runtime.h>
#include <math.h>

#define BB 16
#define SS 1024
#define EE 256
#define HH 8
#define DHD 32
#define MROWS (BB*SS)   // 16384

// ---------------- scratch (static device arrays; no allocation allowed) ----
__device__ float g_ln   [MROWS*EE];
__device__ float g_q    [MROWS*EE];
__device__ float g_k    [MROWS*EE];
__device__ float g_v    [MROWS*EE];
__device__ float g_gate0[MROWS*EE];
__device__ float g_o    [MROWS*EE];
__device__ float g_gate1[MROWS*EE];
__device__ float g_mlp  [MROWS*EE];

// ---------------- tf32 helpers ---------------------------------------------
__device__ __forceinline__ unsigned f2tf(float x) {
    unsigned u;
    asm("cvt.rna.tf32.f32 %0, %1;" : "=r"(u) : "f"(x));
    return u;
}
__device__ __forceinline__ float tfround(float x) {
    return __uint_as_float(f2tf(x));
}

// mma.sync m16n8k8 row.col f32 += tf32 * tf32
__device__ __forceinline__ void mma8(float* c,
    unsigned a0, unsigned a1, unsigned a2, unsigned a3,
    unsigned b0, unsigned b1)
{
    asm volatile(
        "mma.sync.aligned.m16n8k8.row.col.f32.tf32.tf32.f32 "
        "{%0,%1,%2,%3},{%4,%5,%6,%7},{%8,%9},{%0,%1,%2,%3};"
        : "+f"(c[0]), "+f"(c[1]), "+f"(c[2]), "+f"(c[3])
        : "r"(a0), "r"(a1), "r"(a2), "r"(a3), "r"(b0), "r"(b1));
}

// ---------------- block reduction helper (blockDim.x == 256) ---------------
__device__ __forceinline__ float block_sum256(float v, float* sh) {
    #pragma unroll
    for (int o = 16; o > 0; o >>= 1) v += __shfl_xor_sync(0xffffffffu, v, o);
    int w = threadIdx.x >> 5;
    if ((threadIdx.x & 31) == 0) sh[w] = v;
    __syncthreads();
    if (w == 0) {
        float s = (threadIdx.x < 8) ? sh[threadIdx.x] : 0.f;
        #pragma unroll
        for (int o = 4; o > 0; o >>= 1) s += __shfl_xor_sync(0xffffffffu, s, o);
        if (threadIdx.x == 0) sh[0] = s;
    }
    __syncthreads();
    float r = sh[0];
    __syncthreads();
    return r;
}

// ---------------- layernorm of input ---------------------------------------
__global__ __launch_bounds__(256) void ln_kernel(
    const float* __restrict__ x, const float* __restrict__ g,
    const float* __restrict__ b, float* __restrict__ out)
{
    __shared__ float sh[8];
    int row = blockIdx.x;
    int e   = threadIdx.x;
    float v = x[row*EE + e];
    float mean = block_sum256(v, sh) * (1.f/EE);
    float d = v - mean;
    float var = block_sum256(d*d, sh) * (1.f/EE);
    float rstd = rsqrtf(var + 1e-5f);
    out[row*EE + e] = d * rstd * g[e] + b[e];
}

// ---------------- final: out = gate1 * LN(mlp) + gate1 ---------------------
__global__ __launch_bounds__(256) void final_kernel(
    const float* __restrict__ mlp, const float* __restrict__ gate1,
    const float* __restrict__ g, const float* __restrict__ b,
    float* __restrict__ out)
{
    __shared__ float sh[8];
    int row = blockIdx.x;
    int e   = threadIdx.x;
    float v = mlp[row*EE + e];
    float mean = block_sum256(v, sh) * (1.f/EE);
    float d = v - mean;
    float var = block_sum256(d*d, sh) * (1.f/EE);
    float rstd = rsqrtf(var + 1e-5f);
    float lnm = d * rstd * g[e] + b[e];
    float g1 = gate1[row*EE + e];
    out[row*EE + e] = g1 * lnm + g1;
}

// ---------------- split-tf32 tensor-core GEMM ------------------------------
// C[M,256] = A[M,256] @ W[256,256]; block tile 128x128, warp tile 32x64,
// K-chunk 16.  epilogue: 0 = +bias ; 1 = sigmoid(+bias) ; 2 = aux1*(+bias)+aux2
#define APITCH 20
#define BPITCH 132
__global__ __launch_bounds__(256) void gemm_tc(
    const float* __restrict__ A, const float* __restrict__ W,
    const float* __restrict__ bias, float* __restrict__ C,
    const float* __restrict__ aux1, const float* __restrict__ aux2,
    int epi)
{
    __shared__ float Ah[128*APITCH], Al[128*APITCH];
    __shared__ float Bh[16*BPITCH],  Bl[16*BPITCH];

    int tid = threadIdx.x, lane = tid & 31, warp = tid >> 5;
    int wm = warp >> 1, wn = warp & 1;
    int g = lane >> 2, t = lane & 3, t2 = t*2;
    int m0 = blockIdx.y * 128, n0 = blockIdx.x * 128;

    float acc[2][8][4];
    #pragma unroll
    for (int mt = 0; mt < 2; mt++)
        #pragma unroll
        for (int nt = 0; nt < 8; nt++)
            #pragma unroll
            for (int i = 0; i < 4; i++) acc[mt][nt][i] = 0.f;

    for (int k0 = 0; k0 < EE; k0 += 16) {
        // A tile 128x16 -> hi/lo split
        #pragma unroll
        for (int j = 0; j < 2; j++) {
            int idx = tid + j*256;            // float4 index
            int r = idx >> 2, c = (idx & 3) * 4;
            float4 v4 = *(const float4*)&A[(size_t)(m0 + r)*EE + k0 + c];
            float vv[4] = {v4.x, v4.y, v4.z, v4.w};
            #pragma unroll
            for (int i = 0; i < 4; i++) {
                float hf = tfround(vv[i]);
                Ah[r*APITCH + c + i] = hf;
                Al[r*APITCH + c + i] = tfround(vv[i] - hf);
            }
        }
        // B tile 16x128 -> hi/lo split
        #pragma unroll
        for (int j = 0; j < 2; j++) {
            int idx = tid + j*256;
            int r = idx >> 5, c = (idx & 31) * 4;
            float4 v4 = *(const float4*)&W[(size_t)(k0 + r)*EE + n0 + c];
            float vv[4] = {v4.x, v4.y, v4.z, v4.w};
            #pragma unroll
            for (int i = 0; i < 4; i++) {
                float hf = tfround(vv[i]);
                Bh[r*BPITCH + c + i] = hf;
                Bl[r*BPITCH + c + i] = tfround(vv[i] - hf);
            }
        }
        __syncthreads();

        #pragma unroll
        for (int kk = 0; kk < 2; kk++) {
            unsigned ah[2][4], al[2][4];
            #pragma unroll
            for (int mt = 0; mt < 2; mt++) {
                int rb0 = (wm*32 + mt*16 + g)*APITCH + kk*8 + t;
                int rb1 = (wm*32 + mt*16 + g + 8)*APITCH + kk*8 + t;
                ah[mt][0] = __float_as_uint(Ah[rb0]);
                ah[mt][1] = __float_as_uint(Ah[rb1]);
                ah[mt][2] = __float_as_uint(Ah[rb0 + 4]);
                ah[mt][3] = __float_as_uint(Ah[rb1 + 4]);
                al[mt][0] = __float_as_uint(Al[rb0]);
                al[mt][1] = __float_as_uint(Al[rb1]);
                al[mt][2] = __float_as_uint(Al[rb0 + 4]);
                al[mt][3] = __float_as_uint(Al[rb1 + 4]);
            }
            #pragma unroll
            for (int nt = 0; nt < 8; nt++) {
                int cb = wn*64 + nt*8 + g;
                unsigned bh0 = __float_as_uint(Bh[(kk*8 + t    )*BPITCH + cb]);
                unsigned bh1 = __float_as_uint(Bh[(kk*8 + t + 4)*BPITCH + cb]);
                unsigned bl0 = __float_as_uint(Bl[(kk*8 + t    )*BPITCH + cb]);
                unsigned bl1 = __float_as_uint(Bl[(kk*8 + t + 4)*BPITCH + cb]);
                #pragma unroll
                for (int mt = 0; mt < 2; mt++) {
                    mma8(acc[mt][nt], ah[mt][0], ah[mt][1], ah[mt][2], ah[mt][3], bh0, bh1);
                    mma8(acc[mt][nt], ah[mt][0], ah[mt][1], ah[mt][2], ah[mt][3], bl0, bl1);
                    mma8(acc[mt][nt], al[mt][0], al[mt][1], al[mt][2], al[mt][3], bh0, bh1);
                }
            }
        }
        __syncthreads();
    }

    // epilogue
    #pragma unroll
    for (int mt = 0; mt < 2; mt++) {
        int row0 = m0 + wm*32 + mt*16 + g;
        int row1 = row0 + 8;
        #pragma unroll
        for (int nt = 0; nt < 8; nt++) {
            int col = n0 + wn*64 + nt*8 + t2;
            float bv0 = bias[col], bv1 = bias[col + 1];
            float v00 = acc[mt][nt][0] + bv0, v01 = acc[mt][nt][1] + bv1;
            float v10 = acc[mt][nt][2] + bv0, v11 = acc[mt][nt][3] + bv1;
            if (epi == 1) {
                v00 = 1.f/(1.f + __expf(-v00)); v01 = 1.f/(1.f + __expf(-v01));
                v10 = 1.f/(1.f + __expf(-v10)); v11 = 1.f/(1.f + __expf(-v11));
            } else if (epi == 2) {
                size_t i0 = (size_t)row0*EE + col, i1 = (size_t)row1*EE + col;
                float2 a10 = *(const float2*)&aux1[i0];
                float2 a11 = *(const float2*)&aux1[i1];
                float2 a20 = *(const float2*)&aux2[i0];
                float2 a21 = *(const float2*)&aux2[i1];
                v00 = a10.x*v00 + a20.x;  v01 = a10.y*v01 + a20.y;
                v10 = a11.x*v10 + a21.x;  v11 = a11.y*v11 + a21.y;
            }
            *(float2*)&C[(size_t)row0*EE + col] = make_float2(v00, v01);
            *(float2*)&C[(size_t)row1*EE + col] = make_float2(v10, v11);
        }
    }
}

// ---------------- tensor-core flash attention ------------------------------
// grid (B*H, S/64), block 128 (4 warps).  Each warp: 16 q rows.
// K tile 64.  QK^T split-3 tf32; softmax fp32; P@V single tf32.
#define KP 36
#define PP 68
__global__ __launch_bounds__(128) void attn_tc(
    const float* __restrict__ q, const float* __restrict__ k,
    const float* __restrict__ v, const float* __restrict__ rb,
    float* __restrict__ o)
{
    __shared__ float Kh[64*KP], Kl[64*KP], Vs[64*KP], Ps[64*PP];

    int tid = threadIdx.x, lane = tid & 31, wq = tid >> 5;
    int g = lane >> 2, t = lane & 3, t2 = t*2;
    int bh = blockIdx.x, b = bh >> 3, h = bh & 7;
    int q0 = blockIdx.y * 64;
    const float scale = 0.17677669529663687f;   // 1/sqrt(32)

    int r0 = q0 + wq*16 + g;                    // q row within S
    size_t qb0 = (size_t)(b*SS + r0)*EE + h*DHD;
    size_t qb1 = qb0 + (size_t)8*EE;

    unsigned qh[4][4], ql[4][4];
    #pragma unroll
    for (int kk = 0; kk < 4; kk++) {
        int c = kk*8 + t;
        float v00 = q[qb0 + c    ] * scale;
        float v10 = q[qb1 + c    ] * scale;
        float v01 = q[qb0 + c + 4] * scale;
        float v11 = q[qb1 + c + 4] * scale;
        qh[kk][0] = f2tf(v00); ql[kk][0] = f2tf(v00 - __uint_as_float(qh[kk][0]));
        qh[kk][1] = f2tf(v10); ql[kk][1] = f2tf(v10 - __uint_as_float(qh[kk][1]));
        qh[kk][2] = f2tf(v01); ql[kk][2] = f2tf(v01 - __uint_as_float(qh[kk][2]));
        qh[kk][3] = f2tf(v11); ql[kk][3] = f2tf(v11 - __uint_as_float(qh[kk][3]));
    }

    float O[4][4];
    #pragma unroll
    for (int dn = 0; dn < 4; dn++)
        #pragma unroll
        for (int i = 0; i < 4; i++) O[dn][i] = 0.f;
    float m0s = -1e30f, m1s = -1e30f, l0s = 0.f, l1s = 0.f;

    for (int k0 = 0; k0 < SS; k0 += 64) {
        // ---- load K (hi/lo) and V (tf32-rounded) tiles ----
        #pragma unroll
        for (int i = 0; i < 16; i++) {
            int r = i*4 + (tid >> 5), c = tid & 31;
            size_t ga = (size_t)(b*SS + k0 + r)*EE + h*DHD + c;
            float kv = k[ga];
            float hf = tfround(kv);
            Kh[r*KP + c] = hf;
            Kl[r*KP + c] = tfround(kv - hf);
            Vs[r*KP + c] = tfround(v[ga]);
        }
        __syncthreads();

        // ---- scores = bias + q.k ----
        float S_[8][4];
        #pragma unroll
        for (int nt = 0; nt < 8; nt++) {
            const float* bp = &rb[(size_t)r0*SS + k0 + nt*8 + t2];
            float2 b0v = *(const float2*)bp;
            float2 b1v = *(const float2*)(bp + (size_t)8*SS);
            S_[nt][0] = b0v.x; S_[nt][1] = b0v.y;
            S_[nt][2] = b1v.x; S_[nt][3] = b1v.y;
        }
        #pragma unroll
        for (int kk = 0; kk < 4; kk++) {
            #pragma unroll
            for (int nt = 0; nt < 8; nt++) {
                int rbK = (nt*8 + g)*KP + kk*8 + t;
                unsigned bh0 = __float_as_uint(Kh[rbK]);
                unsigned bh1 = __float_as_uint(Kh[rbK + 4]);
                unsigned bl0 = __float_as_uint(Kl[rbK]);
                unsigned bl1 = __float_as_uint(Kl[rbK + 4]);
                mma8(S_[nt], qh[kk][0], qh[kk][1], qh[kk][2], qh[kk][3], bh0, bh1);
                mma8(S_[nt], qh[kk][0], qh[kk][1], qh[kk][2], qh[kk][3], bl0, bl1);
                mma8(S_[nt], ql[kk][0], ql[kk][1], ql[kk][2], ql[kk][3], bh0, bh1);
            }
        }

        // ---- online softmax ----
        float tm0 = -1e30f, tm1 = -1e30f;
        #pragma unroll
        for (int nt = 0; nt < 8; nt++) {
            tm0 = fmaxf(tm0, fmaxf(S_[nt][0], S_[nt][1]));
            tm1 = fmaxf(tm1, fmaxf(S_[nt][2], S_[nt][3]));
        }
        tm0 = fmaxf(tm0, __shfl_xor_sync(0xffffffffu, tm0, 1));
        tm0 = fmaxf(tm0, __shfl_xor_sync(0xffffffffu, tm0, 2));
        tm1 = fmaxf(tm1, __shfl_xor_sync(0xffffffffu, tm1, 1));
        tm1 = fmaxf(tm1, __shfl_xor_sync(0xffffffffu, tm1, 2));
        float nm0 = fmaxf(m0s, tm0), nm1 = fmaxf(m1s, tm1);
        float sc0 = __expf(m0s - nm0), sc1 = __expf(m1s - nm1);
        float rs0 = 0.f, rs1 = 0.f;
        #pragma unroll
        for (int nt = 0; nt < 8; nt++) {
            float p0 = __expf(S_[nt][0] - nm0);
            float p1 = __expf(S_[nt][1] - nm0);
            float p2 = __expf(S_[nt][2] - nm1);
            float p3 = __expf(S_[nt][3] - nm1);
            rs0 += p0 + p1;  rs1 += p2 + p3;
            *(float2*)&Ps[(wq*16 + g    )*PP + nt*8 + t2] = make_float2(tfround(p0), tfround(p1));
            *(float2*)&Ps[(wq*16 + g + 8)*PP + nt*8 + t2] = make_float2(tfround(p2), tfround(p3));
        }
        rs0 += __shfl_xor_sync(0xffffffffu, rs0, 1);
        rs0 += __shfl_xor_sync(0xffffffffu, rs0, 2);
        rs1 += __shfl_xor_sync(0xffffffffu, rs1, 1);
        rs1 += __shfl_xor_sync(0xffffffffu, rs1, 2);
        l0s = l0s*sc0 + rs0;
        l1s = l1s*sc1 + rs1;
        m0s = nm0;  m1s = nm1;
        #pragma unroll
        for (int dn = 0; dn < 4; dn++) {
            O[dn][0] *= sc0; O[dn][1] *= sc0;
            O[dn][2] *= sc1; O[dn][3] *= sc1;
        }
        __syncwarp();

        // ---- O += P @ V ----
        #pragma unroll
        for (int kk = 0; kk < 8; kk++) {
            int pb = (wq*16 + g)*PP + kk*8 + t;
            unsigned a0 = __float_as_uint(Ps[pb]);
            unsigned a1 = __float_as_uint(Ps[pb + 8*PP]);
            unsigned a2 = __float_as_uint(Ps[pb + 4]);
            unsigned a3 = __float_as_uint(Ps[pb + 8*PP + 4]);
            #pragma unroll
            for (int dn = 0; dn < 4; dn++) {
                unsigned b0v = __float_as_uint(Vs[(kk*8 + t    )*KP + dn*8 + g]);
                unsigned b1v = __float_as_uint(Vs[(kk*8 + t + 4)*KP + dn*8 + g]);
                mma8(O[dn], a0, a1, a2, a3, b0v, b1v);
            }
        }
        __syncthreads();
    }

    // ---- write output ----
    float il0 = 1.f / l0s, il1 = 1.f / l1s;
    #pragma unroll
    for (int dn = 0; dn < 4; dn++) {
        size_t ob = (size_t)(b*SS + r0)*EE + h*DHD + dn*8 + t2;
        *(float2*)&o[ob]              = make_float2(O[dn][0]*il0, O[dn][1]*il0);
        *(float2*)&o[ob + (size_t)8*EE] = make_float2(O[dn][2]*il1, O[dn][3]*il1);
    }
}

// ---------------- launch ----------------------------------------------------
extern "C" void kernel_launch(void* const* d_in, const int* in_sizes, int n_in,
                              void* d_out, int out_size)
{
    const float* Matrix = (const float*)d_in[0];
    const float* ln_g   = (const float*)d_in[1];
    const float* ln_b   = (const float*)d_in[2];
    const float* Wq     = (const float*)d_in[3];
    const float* bq     = (const float*)d_in[4];
    const float* Wk     = (const float*)d_in[5];
    const float* bk     = (const float*)d_in[6];
    const float* Wv     = (const float*)d_in[7];
    const float* bv     = (const float*)d_in[8];
    const float* Wo     = (const float*)d_in[9];
    const float* bo     = (const float*)d_in[10];
    const float* rel    = (const float*)d_in[11];
    const float* gW     = (const float*)d_in[12];
    const float* gb     = (const float*)d_in[13];
    const float* mW     = (const float*)d_in[14];
    const float* mb     = (const float*)d_in[15];
    float* out = (float*)d_out;

    float *ln, *qb, *kb, *vb, *gate0, *ob, *gate1, *mlp;
    cudaGetSymbolAddress((void**)&ln,    g_ln);
    cudaGetSymbolAddress((void**)&qb,    g_q);
    cudaGetSymbolAddress((void**)&kb,    g_k);
    cudaGetSymbolAddress((void**)&vb,    g_v);
    cudaGetSymbolAddress((void**)&gate0, g_gate0);
    cudaGetSymbolAddress((void**)&ob,    g_o);
    cudaGetSymbolAddress((void**)&gate1, g_gate1);
    cudaGetSymbolAddress((void**)&mlp,   g_mlp);

    dim3 ggrid(EE/128, MROWS/128);   // (2, 128)

    // 1. ln = LayerNorm(Matrix)
    ln_kernel<<<MROWS, 256>>>(Matrix, ln_g, ln_b, ln);

    // 2. q/k/v projections (from ln), gate0 = sigmoid(Matrix@gW+gb)
    gemm_tc<<<ggrid, 256>>>(ln, Wq, bq, qb, nullptr, nullptr, 0);
    gemm_tc<<<ggrid, 256>>>(ln, Wk, bk, kb, nullptr, nullptr, 0);
    gemm_tc<<<ggrid, 256>>>(ln, Wv, bv, vb, nullptr, nullptr, 0);
    gemm_tc<<<ggrid, 256>>>(Matrix, gW, gb, gate0, nullptr, nullptr, 1);

    // 3. attention -> o
    attn_tc<<<dim3(BB*HH, SS/64), 128>>>(qb, kb, vb, rel, ob);

    // 4. rmha = o@Wo+bo ; fused: gate1 = gate0*rmha + Matrix
    gemm_tc<<<ggrid, 256>>>(ob, Wo, bo, gate1, gate0, Matrix, 2);

    // 5. mlp = sigmoid(gate1@mW+mb)
    gemm_tc<<<ggrid, 256>>>(gate1, mW, mb, mlp, nullptr, nullptr, 1);

    // 6. final = gate1*LN(mlp) + gate1
    final_kernel<<<MROWS, 256>>>(mlp, gate1, ln_g, ln_b, out);
}

// round 3
// speedup vs baseline: 2.1018x; 1.4110x over previous
#include <cuda_runtime.h>
#include <cuda_bf16.h>
#include <math.h>

#define BB 16
#define SS 1024
#define EE 256
#define HH 8
#define DHD 32
#define MROWS (BB*SS)   // 16384

// ---------------- scratch (static device arrays; no allocation allowed) ----
// packed bf16 planes: uint = (bf16 even-k | bf16 odd-k << 16)
__device__ unsigned g_wt[6][2][256*128];     // weight planes, [n][kpair], transposed
__device__ unsigned g_lnh[MROWS*128], g_lnl[MROWS*128];
__device__ unsigned g_mth[MROWS*128], g_mtl[MROWS*128];
__device__ unsigned g_qph[MROWS*128], g_qpl[MROWS*128];
__device__ unsigned g_kph[MROWS*128], g_kpl[MROWS*128];
__device__ unsigned g_vph[MROWS*128], g_vpl[MROWS*128];
__device__ unsigned g_vth[BB*HH*DHD*512], g_vtl[BB*HH*DHD*512];  // [bh*32+d][S/2]
__device__ unsigned g_oph[MROWS*128], g_opl[MROWS*128];
__device__ unsigned g_g1h[MROWS*128], g_g1l[MROWS*128];
__device__ float g_gate0[MROWS*EE], g_gate1[MROWS*EE], g_mlp[MROWS*EE];

// ---------------- helpers ---------------------------------------------------
__device__ __forceinline__ unsigned pk2(float a, float b) {
    __nv_bfloat162 t = __floats2bfloat162_rn(a, b);
    return *reinterpret_cast<unsigned*>(&t);
}
__device__ __forceinline__ void split_pack(float a, float b, unsigned &hi, unsigned &lo) {
    __nv_bfloat16 ah = __float2bfloat16_rn(a);
    __nv_bfloat16 bh = __float2bfloat16_rn(b);
    float ar = a - __bfloat162float(ah);
    float br = b - __bfloat162float(bh);
    __nv_bfloat162 H = __halves2bfloat162(ah, bh);
    __nv_bfloat162 L = __floats2bfloat162_rn(ar, br);
    hi = *reinterpret_cast<unsigned*>(&H);
    lo = *reinterpret_cast<unsigned*>(&L);
}

// mma.sync m16n8k16 row.col f32 += bf16 * bf16
__device__ __forceinline__ void mmabf(float* c,
    unsigned a0, unsigned a1, unsigned a2, unsigned a3,
    unsigned b0, unsigned b1)
{
    asm volatile(
        "mma.sync.aligned.m16n8k16.row.col.f32.bf16.bf16.f32 "
        "{%0,%1,%2,%3},{%4,%5,%6,%7},{%8,%9},{%0,%1,%2,%3};"
        : "+f"(c[0]), "+f"(c[1]), "+f"(c[2]), "+f"(c[3])
        : "r"(a0), "r"(a1), "r"(a2), "r"(a3), "r"(b0), "r"(b1));
}

// ---------------- weight split: W[256][256] -> [n][kpair] hi/lo planes -----
__global__ __launch_bounds__(256) void wsplit(
    const float* __restrict__ Wq, const float* __restrict__ Wk,
    const float* __restrict__ Wv, const float* __restrict__ gW,
    const float* __restrict__ Wo, const float* __restrict__ mW)
{
    const float* W;
    switch (blockIdx.z) {
        case 0: W = Wq; break; case 1: W = Wk; break; case 2: W = Wv; break;
        case 3: W = gW; break; case 4: W = Wo; break; default: W = mW; break;
    }
    __shared__ float s[64][65];
    int k0 = blockIdx.y * 64, n0 = blockIdx.x * 64;
    int tid = threadIdx.x;
    for (int i = tid; i < 4096; i += 256) {
        int r = i >> 6, c = i & 63;
        s[r][c] = W[(size_t)(k0 + r)*EE + n0 + c];
    }
    __syncthreads();
    for (int i = tid; i < 2048; i += 256) {
        int n = i >> 5, kp = i & 31;
        unsigned hi, lo;
        split_pack(s[2*kp][n], s[2*kp+1][n], hi, lo);
        int o = (n0 + n)*128 + k0/2 + kp;
        g_wt[blockIdx.z][0][o] = hi;
        g_wt[blockIdx.z][1][o] = lo;
    }
}

// ---------------- block reduction (blockDim 256) ----------------------------
__device__ __forceinline__ float block_sum256(float v, float* sh) {
    #pragma unroll
    for (int o = 16; o > 0; o >>= 1) v += __shfl_xor_sync(0xffffffffu, v, o);
    int w = threadIdx.x >> 5;
    if ((threadIdx.x & 31) == 0) sh[w] = v;
    __syncthreads();
    if (w == 0) {
        float s = (threadIdx.x < 8) ? sh[threadIdx.x] : 0.f;
        #pragma unroll
        for (int o = 4; o > 0; o >>= 1) s += __shfl_xor_sync(0xffffffffu, s, o);
        if (threadIdx.x == 0) sh[0] = s;
    }
    __syncthreads();
    float r = sh[0];
    __syncthreads();
    return r;
}

// ---------------- LN of input -> ln planes + Matrix planes ------------------
__global__ __launch_bounds__(256) void ln_kernel(
    const float* __restrict__ x, const float* __restrict__ g,
    const float* __restrict__ b)
{
    __shared__ float shv[256], shx[256], sh[8];
    int row = blockIdx.x, e = threadIdx.x;
    float xv = x[(size_t)row*EE + e];
    float mean = block_sum256(xv, sh) * (1.f/EE);
    float d = xv - mean;
    float var = block_sum256(d*d, sh) * (1.f/EE);
    float rstd = rsqrtf(var + 1e-5f);
    float lnv = d * rstd * g[e] + b[e];
    shx[e] = xv; shv[e] = lnv;
    __syncthreads();
    if (e < 128) {
        unsigned hi, lo;
        split_pack(shv[2*e], shv[2*e+1], hi, lo);
        g_lnh[row*128 + e] = hi;  g_lnl[row*128 + e] = lo;
        split_pack(shx[2*e], shx[2*e+1], hi, lo);
        g_mth[row*128 + e] = hi;  g_mtl[row*128 + e] = lo;
    }
}

// ---------------- final: out = gate1 * LN(mlp) + gate1 ----------------------
__global__ __launch_bounds__(256) void final_kernel(
    const float* __restrict__ g, const float* __restrict__ b,
    float* __restrict__ out)
{
    __shared__ float sh[8];
    int row = blockIdx.x, e = threadIdx.x;
    float v = g_mlp[(size_t)row*EE + e];
    float mean = block_sum256(v, sh) * (1.f/EE);
    float d = v - mean;
    float var = block_sum256(d*d, sh) * (1.f/EE);
    float rstd = rsqrtf(var + 1e-5f);
    float lnm = d * rstd * g[e] + b[e];
    float g1 = g_gate1[(size_t)row*EE + e];
    out[(size_t)row*EE + e] = g1 * lnm + g1;
}

// ---------------- bf16 split-2 tensor-core GEMM -----------------------------
// C[M,256] = A[M,256] @ W[256,256], block tile 128x64, 8 warps (4m x 2n),
// warp tile 32x32. K chunk 32 (16 pairs), reg prefetch, smem single-buffer.
// ops: 0=Q 1=K 2=V (epi: planes) 3=gate0 (sigmoid fp32)
//      4=Wo (gate1 = gate0*(.)+Matrix, fp32 + planes) 5=mW (sigmoid fp32 mlp)
__global__ __launch_bounds__(256) void gemm_bf16(
    const float* __restrict__ bq, const float* __restrict__ bk,
    const float* __restrict__ bv, const float* __restrict__ gb,
    const float* __restrict__ bo, const float* __restrict__ mb,
    const float* __restrict__ Matrix, int op_base)
{
    int op = op_base + blockIdx.z;
    const unsigned *Ah, *Al;
    const float* bias;
    switch (op) {
        case 0: Ah = g_lnh; Al = g_lnl; bias = bq; break;
        case 1: Ah = g_lnh; Al = g_lnl; bias = bk; break;
        case 2: Ah = g_lnh; Al = g_lnl; bias = bv; break;
        case 3: Ah = g_mth; Al = g_mtl; bias = gb; break;
        case 4: Ah = g_oph; Al = g_opl; bias = bo; break;
        default: Ah = g_g1h; Al = g_g1l; bias = mb; break;
    }
    const unsigned* Wh = g_wt[op][0];
    const unsigned* Wl = g_wt[op][1];

    __shared__ unsigned sA[2][128*17];
    __shared__ unsigned sB[2][64*17];

    int tid = threadIdx.x, lane = tid & 31, warp = tid >> 5;
    int wm = warp >> 1, wn = warp & 1;
    int g = lane >> 2, t = lane & 3;
    int m0 = blockIdx.y * 128, n0 = blockIdx.x * 64;

    float acc[2][4][4];
    #pragma unroll
    for (int mt = 0; mt < 2; mt++)
        #pragma unroll
        for (int nt = 0; nt < 4; nt++)
            #pragma unroll
            for (int i = 0; i < 4; i++) acc[mt][nt][i] = 0.f;

    // prefetch regs: A 2 uint4 per plane, B 1 uint4 per plane
    uint4 ra[2][2], rb[2];
    int arow[2], af4[2], brow, bf4;
    #pragma unroll
    for (int j = 0; j < 2; j++) { int idx = tid + j*256; arow[j] = idx >> 2; af4[j] = idx & 3; }
    brow = tid >> 2; bf4 = tid & 3;

    #pragma unroll 1
    for (int c = 0; c < 8; c++) {
        if (c == 0) {
            #pragma unroll
            for (int j = 0; j < 2; j++) {
                ra[0][j] = *(const uint4*)&Ah[(size_t)(m0 + arow[j])*128 + af4[j]*4];
                ra[1][j] = *(const uint4*)&Al[(size_t)(m0 + arow[j])*128 + af4[j]*4];
            }
            rb[0] = *(const uint4*)&Wh[(size_t)(n0 + brow)*128 + bf4*4];
            rb[1] = *(const uint4*)&Wl[(size_t)(n0 + brow)*128 + bf4*4];
        }
        // store staged chunk
        #pragma unroll
        for (int pl = 0; pl < 2; pl++) {
            #pragma unroll
            for (int j = 0; j < 2; j++) {
                int o = arow[j]*17 + af4[j]*4;
                sA[pl][o+0] = (&ra[pl][j].x)[0]; sA[pl][o+1] = (&ra[pl][j].x)[1];
                sA[pl][o+2] = (&ra[pl][j].x)[2]; sA[pl][o+3] = (&ra[pl][j].x)[3];
            }
            int o = brow*17 + bf4*4;
            sB[pl][o+0] = (&rb[pl].x)[0]; sB[pl][o+1] = (&rb[pl].x)[1];
            sB[pl][o+2] = (&rb[pl].x)[2]; sB[pl][o+3] = (&rb[pl].x)[3];
        }
        __syncthreads();
        if (c < 7) {
            int cc = (c+1)*16;
            #pragma unroll
            for (int j = 0; j < 2; j++) {
                ra[0][j] = *(const uint4*)&Ah[(size_t)(m0 + arow[j])*128 + cc + af4[j]*4];
                ra[1][j] = *(const uint4*)&Al[(size_t)(m0 + arow[j])*128 + cc + af4[j]*4];
            }
            rb[0] = *(const uint4*)&Wh[(size_t)(n0 + brow)*128 + cc + bf4*4];
            rb[1] = *(const uint4*)&Wl[(size_t)(n0 + brow)*128 + cc + bf4*4];
        }
        // mma phase: 2 k16 sub-chunks
        #pragma unroll
        for (int kk = 0; kk < 2; kk++) {
            unsigned ah[2][4], al[2][4];
            #pragma unroll
            for (int mt = 0; mt < 2; mt++) {
                int b0 = (wm*32 + mt*16 + g)*17 + kk*8 + t;
                int b1 = b0 + 8*17;
                ah[mt][0] = sA[0][b0]; ah[mt][1] = sA[0][b1];
                ah[mt][2] = sA[0][b0+4]; ah[mt][3] = sA[0][b1+4];
                al[mt][0] = sA[1][b0]; al[mt][1] = sA[1][b1];
                al[mt][2] = sA[1][b0+4]; al[mt][3] = sA[1][b1+4];
            }
            #pragma unroll
            for (int nt = 0; nt < 4; nt++) {
                int cb = (wn*32 + nt*8 + g)*17 + kk*8 + t;
                unsigned bh0 = sB[0][cb], bh1 = sB[0][cb+4];
                unsigned bl0 = sB[1][cb], bl1 = sB[1][cb+4];
                #pragma unroll
                for (int mt = 0; mt < 2; mt++) {
                    mmabf(acc[mt][nt], ah[mt][0], ah[mt][1], ah[mt][2], ah[mt][3], bh0, bh1);
                    mmabf(acc[mt][nt], ah[mt][0], ah[mt][1], ah[mt][2], ah[mt][3], bl0, bl1);
                    mmabf(acc[mt][nt], al[mt][0], al[mt][1], al[mt][2], al[mt][3], bh0, bh1);
                }
            }
        }
        __syncthreads();
    }

    // epilogue
    #pragma unroll
    for (int mt = 0; mt < 2; mt++) {
        int row0 = m0 + wm*32 + mt*16 + g;
        int row1 = row0 + 8;
        #pragma unroll
        for (int nt = 0; nt < 4; nt++) {
            int col = n0 + wn*32 + nt*8 + t*2;
            int cp  = col >> 1;
            float bv0 = bias[col], bv1 = bias[col+1];
            float v00 = acc[mt][nt][0] + bv0, v01 = acc[mt][nt][1] + bv1;
            float v10 = acc[mt][nt][2] + bv0, v11 = acc[mt][nt][3] + bv1;
            if (op <= 2) {
                unsigned *ph, *pl_;
                if (op == 0)      { ph = g_qph; pl_ = g_qpl; }
                else if (op == 1) { ph = g_kph; pl_ = g_kpl; }
                else              { ph = g_vph; pl_ = g_vpl; }
                unsigned hi, lo;
                split_pack(v00, v01, hi, lo);
                ph[row0*128 + cp] = hi;  pl_[row0*128 + cp] = lo;
                split_pack(v10, v11, hi, lo);
                ph[row1*128 + cp] = hi;  pl_[row1*128 + cp] = lo;
            } else if (op == 3 || op == 5) {
                float* dst = (op == 3) ? g_gate0 : g_mlp;
                v00 = 1.f/(1.f + __expf(-v00)); v01 = 1.f/(1.f + __expf(-v01));
                v10 = 1.f/(1.f + __expf(-v10)); v11 = 1.f/(1.f + __expf(-v11));
                *(float2*)&dst[(size_t)row0*EE + col] = make_float2(v00, v01);
                *(float2*)&dst[(size_t)row1*EE + col] = make_float2(v10, v11);
            } else {  // op 4: gate1 = gate0*rmha + Matrix, + planes
                size_t i0 = (size_t)row0*EE + col, i1 = (size_t)row1*EE + col;
                float2 ga0 = *(const float2*)&g_gate0[i0];
                float2 ga1 = *(const float2*)&g_gate0[i1];
                float2 mx0 = *(const float2*)&Matrix[i0];
                float2 mx1 = *(const float2*)&Matrix[i1];
                v00 = ga0.x*v00 + mx0.x;  v01 = ga0.y*v01 + mx0.y;
                v10 = ga1.x*v10 + mx1.x;  v11 = ga1.y*v11 + mx1.y;
                *(float2*)&g_gate1[i0] = make_float2(v00, v01);
                *(float2*)&g_gate1[i1] = make_float2(v10, v11);
                unsigned hi, lo;
                split_pack(v00, v01, hi, lo);
                g_g1h[row0*128 + cp] = hi;  g_g1l[row0*128 + cp] = lo;
                split_pack(v10, v11, hi, lo);
                g_g1h[row1*128 + cp] = hi;  g_g1l[row1*128 + cp] = lo;
            }
        }
    }
}

// ---------------- V repack: [row][dh-pair] planes -> [d][kv-pair] -----------
__global__ __launch_bounds__(256) void vrepack()
{
    __shared__ unsigned s[2][128*17];
    int bh = blockIdx.x, b = bh >> 3, hd = bh & 7;
    int k0 = blockIdx.y * 128;
    int tid = threadIdx.x;
    for (int i = tid; i < 2048; i += 256) {
        int r = i >> 4, dp = i & 15;
        size_t ga = (size_t)(b*SS + k0 + r)*128 + hd*16 + dp;
        s[0][r*17 + dp] = g_vph[ga];
        s[1][r*17 + dp] = g_vpl[ga];
    }
    __syncthreads();
    for (int i = tid; i < 2048; i += 256) {
        int kp = i & 63, d = i >> 6;
        unsigned sel = (d & 1) ? 0x7632u : 0x5410u;
        #pragma unroll
        for (int pl = 0; pl < 2; pl++) {
            unsigned u0 = s[pl][(2*kp)*17 + (d >> 1)];
            unsigned u1 = s[pl][(2*kp+1)*17 + (d >> 1)];
            unsigned val = __byte_perm(u0, u1, sel);
            unsigned* dst = pl ? g_vtl : g_vth;
            dst[(size_t)(bh*32 + d)*512 + k0/2 + kp] = val;
        }
    }
}

// ---------------- bf16 tensor-core flash attention --------------------------
// grid (B*H, S/64), block 128 (4 warps), warp = 16 q rows, kv tile 64.
__global__ __launch_bounds__(128) void attn_bf(
    const float* __restrict__ rb, float* /*unused*/)
{
    __shared__ unsigned sKh[64*17], sKl[64*17];
    __shared__ unsigned sVh[32*36], sVl[32*36];
    __shared__ unsigned sP[64*36];

    int tid = threadIdx.x, lane = tid & 31, wq = tid >> 5;
    int g = lane >> 2, t = lane & 3, t2 = t*2;
    int bh = blockIdx.x, b = bh >> 3, hd = bh & 7;
    int q0 = blockIdx.y * 64;
    const float scale = 0.17677669529663687f;

    int r0 = q0 + wq*16 + g;
    int qrow0 = b*SS + r0, qrow1 = qrow0 + 8;

    unsigned qhf[2][4], qlf[2][4];
    #pragma unroll
    for (int kk = 0; kk < 2; kk++) {
        int b0 = qrow0*128 + hd*16 + kk*8 + t;
        int b1 = qrow1*128 + hd*16 + kk*8 + t;
        qhf[kk][0] = g_qph[b0]; qhf[kk][1] = g_qph[b1];
        qhf[kk][2] = g_qph[b0+4]; qhf[kk][3] = g_qph[b1+4];
        qlf[kk][0] = g_qpl[b0]; qlf[kk][1] = g_qpl[b1];
        qlf[kk][2] = g_qpl[b0+4]; qlf[kk][3] = g_qpl[b1+4];
    }

    float O[4][4];
    #pragma unroll
    for (int dn = 0; dn < 4; dn++)
        #pragma unroll
        for (int i = 0; i < 4; i++) O[dn][i] = 0.f;
    float m0s = -1e30f, m1s = -1e30f, l0s = 0.f, l1s = 0.f;

    for (int k0 = 0; k0 < SS; k0 += 64) {
        // K tiles: [64 kv][16 dh-pairs]
        #pragma unroll
        for (int j = 0; j < 2; j++) {
            int idx = tid + j*128;
            int r = idx >> 2, f4 = idx & 3;
            size_t ga = (size_t)(b*SS + k0 + r)*128 + hd*16 + f4*4;
            uint4 vh = *(const uint4*)&g_kph[ga];
            uint4 vl = *(const uint4*)&g_kpl[ga];
            int o = r*17 + f4*4;
            sKh[o]=vh.x; sKh[o+1]=vh.y; sKh[o+2]=vh.z; sKh[o+3]=vh.w;
            sKl[o]=vl.x; sKl[o+1]=vl.y; sKl[o+2]=vl.z; sKl[o+3]=vl.w;
        }
        // V tiles: [32 d][32 kv-pairs]
        #pragma unroll
        for (int j = 0; j < 2; j++) {
            int idx = tid + j*128;
            int d = idx >> 3, f4 = idx & 7;
            size_t ga = (size_t)(bh*32 + d)*512 + k0/2 + f4*4;
            *(uint4*)&sVh[d*36 + f4*4] = *(const uint4*)&g_vth[ga];
            *(uint4*)&sVl[d*36 + f4*4] = *(const uint4*)&g_vtl[ga];
        }
        __syncthreads();

        // scores
        float S_[8][4];
        #pragma unroll
        for (int nt = 0; nt < 8; nt++)
            #pragma unroll
            for (int i = 0; i < 4; i++) S_[nt][i] = 0.f;
        #pragma unroll
        for (int kk = 0; kk < 2; kk++) {
            #pragma unroll
            for (int nt = 0; nt < 8; nt++) {
                int cb = (nt*8 + g)*17 + kk*8 + t;
                unsigned kh0 = sKh[cb], kh1 = sKh[cb+4];
                unsigned kl0 = sKl[cb], kl1 = sKl[cb+4];
                mmabf(S_[nt], qhf[kk][0], qhf[kk][1], qhf[kk][2], qhf[kk][3], kh0, kh1);
                mmabf(S_[nt], qhf[kk][0], qhf[kk][1], qhf[kk][2], qhf[kk][3], kl0, kl1);
                mmabf(S_[nt], qlf[kk][0], qlf[kk][1], qlf[kk][2], qlf[kk][3], kh0, kh1);
            }
        }
        #pragma unroll
        for (int nt = 0; nt < 8; nt++) {
            const float* bp = &rb[(size_t)r0*SS + k0 + nt*8 + t2];
            float2 b0v = *(const float2*)bp;
            float2 b1v = *(const float2*)(bp + (size_t)8*SS);
            S_[nt][0] = S_[nt][0]*scale + b0v.x;
            S_[nt][1] = S_[nt][1]*scale + b0v.y;
            S_[nt][2] = S_[nt][2]*scale + b1v.x;
            S_[nt][3] = S_[nt][3]*scale + b1v.y;
        }

        // online softmax
        float tm0 = -1e30f, tm1 = -1e30f;
        #pragma unroll
        for (int nt = 0; nt < 8; nt++) {
            tm0 = fmaxf(tm0, fmaxf(S_[nt][0], S_[nt][1]));
            tm1 = fmaxf(tm1, fmaxf(S_[nt][2], S_[nt][3]));
        }
        tm0 = fmaxf(tm0, __shfl_xor_sync(0xffffffffu, tm0, 1));
        tm0 = fmaxf(tm0, __shfl_xor_sync(0xffffffffu, tm0, 2));
        tm1 = fmaxf(tm1, __shfl_xor_sync(0xffffffffu, tm1, 1));
        tm1 = fmaxf(tm1, __shfl_xor_sync(0xffffffffu, tm1, 2));
        float nm0 = fmaxf(m0s, tm0), nm1 = fmaxf(m1s, tm1);
        float sc0 = __expf(m0s - nm0), sc1 = __expf(m1s - nm1);
        float rs0 = 0.f, rs1 = 0.f;
        int pr0 = (wq*16 + g)*36, pr1 = pr0 + 8*36;
        #pragma unroll
        for (int nt = 0; nt < 8; nt++) {
            float p0 = __expf(S_[nt][0] - nm0);
            float p1 = __expf(S_[nt][1] - nm0);
            float p2 = __expf(S_[nt][2] - nm1);
            float p3 = __expf(S_[nt][3] - nm1);
            rs0 += p0 + p1;  rs1 += p2 + p3;
            sP[pr0 + nt*4 + t] = pk2(p0, p1);
            sP[pr1 + nt*4 + t] = pk2(p2, p3);
        }
        rs0 += __shfl_xor_sync(0xffffffffu, rs0, 1);
        rs0 += __shfl_xor_sync(0xffffffffu, rs0, 2);
        rs1 += __shfl_xor_sync(0xffffffffu, rs1, 1);
        rs1 += __shfl_xor_sync(0xffffffffu, rs1, 2);
        l0s = l0s*sc0 + rs0;
        l1s = l1s*sc1 + rs1;
        m0s = nm0;  m1s = nm1;
        #pragma unroll
        for (int dn = 0; dn < 4; dn++) {
            O[dn][0] *= sc0; O[dn][1] *= sc0;
            O[dn][2] *= sc1; O[dn][3] *= sc1;
        }
        __syncwarp();

        // O += P @ V  (P hi-only, V hi+lo)
        #pragma unroll
        for (int kk = 0; kk < 4; kk++) {
            int pa = pr0 + kk*8 + t;
            unsigned a0 = sP[pa], a1 = sP[pa + 8*36];
            unsigned a2 = sP[pa+4], a3 = sP[pa + 8*36 + 4];
            #pragma unroll
            for (int dn = 0; dn < 4; dn++) {
                int vb = (dn*8 + g)*36 + kk*8 + t;
                mmabf(O[dn], a0, a1, a2, a3, sVh[vb], sVh[vb+4]);
                mmabf(O[dn], a0, a1, a2, a3, sVl[vb], sVl[vb+4]);
            }
        }
        __syncthreads();
    }

    float il0 = 1.f/l0s, il1 = 1.f/l1s;
    #pragma unroll
    for (int dn = 0; dn < 4; dn++) {
        int cp = hd*16 + dn*4 + t;
        unsigned hi, lo;
        split_pack(O[dn][0]*il0, O[dn][1]*il0, hi, lo);
        g_oph[qrow0*128 + cp] = hi;  g_opl[qrow0*128 + cp] = lo;
        split_pack(O[dn][2]*il1, O[dn][3]*il1, hi, lo);
        g_oph[qrow1*128 + cp] = hi;  g_opl[qrow1*128 + cp] = lo;
    }
}

// ---------------- launch ----------------------------------------------------
extern "C" void kernel_launch(void* const* d_in, const int* in_sizes, int n_in,
                              void* d_out, int out_size)
{
    const float* Matrix = (const float*)d_in[0];
    const float* ln_g   = (const float*)d_in[1];
    const float* ln_b   = (const float*)d_in[2];
    const float* Wq     = (const float*)d_in[3];
    const float* bq     = (const float*)d_in[4];
    const float* Wk     = (const float*)d_in[5];
    const float* bk     = (const float*)d_in[6];
    const float* Wv     = (const float*)d_in[7];
    const float* bv     = (const float*)d_in[8];
    const float* Wo     = (const float*)d_in[9];
    const float* bo     = (const float*)d_in[10];
    const float* rel    = (const float*)d_in[11];
    const float* gW     = (const float*)d_in[12];
    const float* gb     = (const float*)d_in[13];
    const float* mW     = (const float*)d_in[14];
    const float* mb     = (const float*)d_in[15];
    float* out = (float*)d_out;

    // weights -> planes ; input LN + Matrix planes
    wsplit<<<dim3(4,4,6), 256>>>(Wq, Wk, Wv, gW, Wo, mW);
    ln_kernel<<<MROWS, 256>>>(Matrix, ln_g, ln_b);

    // fused QKV + gate0 (ops 0..3), 2048 blocks
    gemm_bf16<<<dim3(4,128,4), 256>>>(bq, bk, bv, gb, bo, mb, Matrix, 0);

    // V transpose planes, then attention
    vrepack<<<dim3(128,8), 256>>>();
    attn_bf<<<dim3(BB*HH, SS/64), 128>>>(rel, nullptr);

    // Wo GEMM (op4: gate1), then mW GEMM (op5: mlp)
    gemm_bf16<<<dim3(4,128,1), 256>>>(bq, bk, bv, gb, bo, mb, Matrix, 4);
    gemm_bf16<<<dim3(4,128,1), 256>>>(bq, bk, bv, gb, bo, mb, Matrix, 5);

    // final
    final_kernel<<<MROWS, 256>>>(ln_g, ln_b, out);
}

// round 4
// speedup vs baseline: 2.4203x; 1.1515x over previous
#include <cuda_runtime.h>
#include <cuda_fp16.h>
#include <math.h>

#define BB 16
#define SS 1024
#define EE 256
#define HH 8
#define DHD 32
#define MROWS (BB*SS)   // 16384

// ---------------- scratch (static device arrays; no allocation allowed) ----
// packed fp16 planes: uint = (h16 even-k | h16 odd-k << 16)
__device__ unsigned g_wt[6][2][256*128];     // weight planes [n][kpair] hi/lo
__device__ unsigned g_lnh[MROWS*128];
__device__ unsigned g_mth[MROWS*128];
__device__ unsigned g_qph[MROWS*128];
__device__ unsigned g_kph[MROWS*128], g_kpl[MROWS*128];
__device__ unsigned g_vph[MROWS*128];
__device__ unsigned g_vth[BB*HH*DHD*512];    // [bh*32+d][S/2] transposed V hi
__device__ unsigned g_oph[MROWS*128], g_opl[MROWS*128];
__device__ unsigned g_g1h[MROWS*128], g_g1l[MROWS*128];
__device__ float g_gate0[MROWS*EE], g_gate1[MROWS*EE], g_mlp[MROWS*EE];

// ---------------- helpers ---------------------------------------------------
__device__ __forceinline__ unsigned pkh(float a, float b) {
    __half2 t = __floats2half2_rn(a, b);
    return *reinterpret_cast<unsigned*>(&t);
}
__device__ __forceinline__ void split_pack(float a, float b, unsigned &hi, unsigned &lo) {
    __half ah = __float2half_rn(a);
    __half bh = __float2half_rn(b);
    float ar = a - __half2float(ah);
    float br = b - __half2float(bh);
    __half2 H = __halves2half2(ah, bh);
    __half2 L = __floats2half2_rn(ar, br);
    hi = *reinterpret_cast<unsigned*>(&H);
    lo = *reinterpret_cast<unsigned*>(&L);
}

// mma.sync m16n8k16 row.col f32 += f16 * f16
__device__ __forceinline__ void mmah(float* c,
    unsigned a0, unsigned a1, unsigned a2, unsigned a3,
    unsigned b0, unsigned b1)
{
    asm volatile(
        "mma.sync.aligned.m16n8k16.row.col.f32.f16.f16.f32 "
        "{%0,%1,%2,%3},{%4,%5,%6,%7},{%8,%9},{%0,%1,%2,%3};"
        : "+f"(c[0]), "+f"(c[1]), "+f"(c[2]), "+f"(c[3])
        : "r"(a0), "r"(a1), "r"(a2), "r"(a3), "r"(b0), "r"(b1));
}

// ---------------- weight split: W[256][256] -> [n][kpair] hi/lo planes -----
__global__ __launch_bounds__(256) void wsplit(
    const float* __restrict__ Wq, const float* __restrict__ Wk,
    const float* __restrict__ Wv, const float* __restrict__ gW,
    const float* __restrict__ Wo, const float* __restrict__ mW)
{
    const float* W;
    switch (blockIdx.z) {
        case 0: W = Wq; break; case 1: W = Wk; break; case 2: W = Wv; break;
        case 3: W = gW; break; case 4: W = Wo; break; default: W = mW; break;
    }
    __shared__ float s[64][65];
    int k0 = blockIdx.y * 64, n0 = blockIdx.x * 64;
    int tid = threadIdx.x;
    for (int i = tid; i < 4096; i += 256) {
        int r = i >> 6, c = i & 63;
        s[r][c] = W[(size_t)(k0 + r)*EE + n0 + c];
    }
    __syncthreads();
    for (int i = tid; i < 2048; i += 256) {
        int n = i >> 5, kp = i & 31;
        unsigned hi, lo;
        split_pack(s[2*kp][n], s[2*kp+1][n], hi, lo);
        int o = (n0 + n)*128 + k0/2 + kp;
        g_wt[blockIdx.z][0][o] = hi;
        g_wt[blockIdx.z][1][o] = lo;
    }
}

// ---------------- warp reductions -------------------------------------------
__device__ __forceinline__ float wsum(float v) {
    #pragma unroll
    for (int o = 16; o > 0; o >>= 1) v += __shfl_xor_sync(0xffffffffu, v, o);
    return v;
}

// ---------------- LN of input -> ln hi plane + Matrix hi plane --------------
// warp per row; grid MROWS/8, block 256
__global__ __launch_bounds__(256) void ln_kernel(
    const float* __restrict__ x, const float* __restrict__ g,
    const float* __restrict__ b)
{
    int warp = threadIdx.x >> 5, lane = threadIdx.x & 31;
    int row = blockIdx.x*8 + warp;
    const float* xr = x + (size_t)row*EE + lane*8;
    float4 a0 = *(const float4*)xr;
    float4 a1 = *(const float4*)(xr + 4);
    float xv[8] = {a0.x,a0.y,a0.z,a0.w,a1.x,a1.y,a1.z,a1.w};
    float s = 0.f;
    #pragma unroll
    for (int i = 0; i < 8; i++) s += xv[i];
    float mean = wsum(s) * (1.f/EE);
    float vs = 0.f;
    #pragma unroll
    for (int i = 0; i < 8; i++) { float d = xv[i]-mean; vs += d*d; }
    float rstd = rsqrtf(wsum(vs)*(1.f/EE) + 1e-5f);
    float4 g0 = *(const float4*)(g + lane*8);
    float4 g1 = *(const float4*)(g + lane*8 + 4);
    float4 b0 = *(const float4*)(b + lane*8);
    float4 b1 = *(const float4*)(b + lane*8 + 4);
    float gg[8] = {g0.x,g0.y,g0.z,g0.w,g1.x,g1.y,g1.z,g1.w};
    float bb[8] = {b0.x,b0.y,b0.z,b0.w,b1.x,b1.y,b1.z,b1.w};
    float ln[8];
    #pragma unroll
    for (int i = 0; i < 8; i++) ln[i] = (xv[i]-mean)*rstd*gg[i] + bb[i];
    uint4 u, um;
    u.x = pkh(ln[0],ln[1]); u.y = pkh(ln[2],ln[3]);
    u.z = pkh(ln[4],ln[5]); u.w = pkh(ln[6],ln[7]);
    um.x = pkh(xv[0],xv[1]); um.y = pkh(xv[2],xv[3]);
    um.z = pkh(xv[4],xv[5]); um.w = pkh(xv[6],xv[7]);
    *(uint4*)&g_lnh[row*128 + lane*4] = u;
    *(uint4*)&g_mth[row*128 + lane*4] = um;
}

// ---------------- final: out = gate1 * LN(mlp) + gate1 ----------------------
__global__ __launch_bounds__(256) void final_kernel(
    const float* __restrict__ g, const float* __restrict__ b,
    float* __restrict__ out)
{
    int warp = threadIdx.x >> 5, lane = threadIdx.x & 31;
    int row = blockIdx.x*8 + warp;
    const float* mr = g_mlp + (size_t)row*EE + lane*8;
    float4 a0 = *(const float4*)mr;
    float4 a1 = *(const float4*)(mr + 4);
    float xv[8] = {a0.x,a0.y,a0.z,a0.w,a1.x,a1.y,a1.z,a1.w};
    float s = 0.f;
    #pragma unroll
    for (int i = 0; i < 8; i++) s += xv[i];
    float mean = wsum(s) * (1.f/EE);
    float vs = 0.f;
    #pragma unroll
    for (int i = 0; i < 8; i++) { float d = xv[i]-mean; vs += d*d; }
    float rstd = rsqrtf(wsum(vs)*(1.f/EE) + 1e-5f);
    float4 g0 = *(const float4*)(g + lane*8);
    float4 g1v = *(const float4*)(g + lane*8 + 4);
    float4 b0 = *(const float4*)(b + lane*8);
    float4 b1 = *(const float4*)(b + lane*8 + 4);
    float gg[8] = {g0.x,g0.y,g0.z,g0.w,g1v.x,g1v.y,g1v.z,g1v.w};
    float bb[8] = {b0.x,b0.y,b0.z,b0.w,b1.x,b1.y,b1.z,b1.w};
    const float* gr = g_gate1 + (size_t)row*EE + lane*8;
    float4 q0 = *(const float4*)gr;
    float4 q1 = *(const float4*)(gr + 4);
    float gv[8] = {q0.x,q0.y,q0.z,q0.w,q1.x,q1.y,q1.z,q1.w};
    float o[8];
    #pragma unroll
    for (int i = 0; i < 8; i++) {
        float lnm = (xv[i]-mean)*rstd*gg[i] + bb[i];
        o[i] = gv[i]*lnm + gv[i];
    }
    float* orow = out + (size_t)row*EE + lane*8;
    *(float4*)orow       = make_float4(o[0],o[1],o[2],o[3]);
    *(float4*)(orow + 4) = make_float4(o[4],o[5],o[6],o[7]);
}

// ---------------- fp16 tensor-core GEMM -------------------------------------
// C[M,256]=A[M,256]@W[256,256]; block 128x64, 8 warps (4m x 2n), warp 32x32.
// ops 0..3: 2-pass (ah*bh + ah*bl); ops 4,5: 3-pass (+ al*bh).
// epilogues: 0=Q(hi) 1=K(hi+lo) 2=V(hi) 3=gate0 sigmoid fp32
//            4=gate1=gate0*(.)+Matrix (fp32 + hi/lo planes) 5=mlp sigmoid fp32
__global__ __launch_bounds__(256) void gemm_h(
    const float* __restrict__ bq, const float* __restrict__ bk,
    const float* __restrict__ bv, const float* __restrict__ gb,
    const float* __restrict__ bo, const float* __restrict__ mb,
    const float* __restrict__ Matrix, int op_base)
{
    int op = op_base + blockIdx.z;
    const unsigned *Ah, *Al = nullptr;
    const float* bias;
    switch (op) {
        case 0: Ah = g_lnh; bias = bq; break;
        case 1: Ah = g_lnh; bias = bk; break;
        case 2: Ah = g_lnh; bias = bv; break;
        case 3: Ah = g_mth; bias = gb; break;
        case 4: Ah = g_oph; Al = g_opl; bias = bo; break;
        default: Ah = g_g1h; Al = g_g1l; bias = mb; break;
    }
    bool p3 = (op >= 4);
    const unsigned* Wh = g_wt[op][0];
    const unsigned* Wl = g_wt[op][1];

    __shared__ unsigned sA[2][128*17];
    __shared__ unsigned sB[2][64*17];

    int tid = threadIdx.x, lane = tid & 31, warp = tid >> 5;
    int wm = warp >> 1, wn = warp & 1;
    int g = lane >> 2, t = lane & 3;
    int m0 = blockIdx.y * 128, n0 = blockIdx.x * 64;

    float acc[2][4][4];
    #pragma unroll
    for (int mt = 0; mt < 2; mt++)
        #pragma unroll
        for (int nt = 0; nt < 4; nt++)
            #pragma unroll
            for (int i = 0; i < 4; i++) acc[mt][nt][i] = 0.f;

    uint4 rah[2], ral[2], rbv[2];
    int arow[2], af4[2], brow, bf4;
    #pragma unroll
    for (int j = 0; j < 2; j++) { int idx = tid + j*256; arow[j] = idx >> 2; af4[j] = idx & 3; }
    brow = tid >> 2; bf4 = tid & 3;

    #pragma unroll 1
    for (int c = 0; c < 8; c++) {
        if (c == 0) {
            #pragma unroll
            for (int j = 0; j < 2; j++)
                rah[j] = *(const uint4*)&Ah[(size_t)(m0 + arow[j])*128 + af4[j]*4];
            if (p3) {
                #pragma unroll
                for (int j = 0; j < 2; j++)
                    ral[j] = *(const uint4*)&Al[(size_t)(m0 + arow[j])*128 + af4[j]*4];
            }
            rbv[0] = *(const uint4*)&Wh[(size_t)(n0 + brow)*128 + bf4*4];
            rbv[1] = *(const uint4*)&Wl[(size_t)(n0 + brow)*128 + bf4*4];
        }
        #pragma unroll
        for (int j = 0; j < 2; j++) {
            int o = arow[j]*17 + af4[j]*4;
            sA[0][o+0] = (&rah[j].x)[0]; sA[0][o+1] = (&rah[j].x)[1];
            sA[0][o+2] = (&rah[j].x)[2]; sA[0][o+3] = (&rah[j].x)[3];
        }
        if (p3) {
            #pragma unroll
            for (int j = 0; j < 2; j++) {
                int o = arow[j]*17 + af4[j]*4;
                sA[1][o+0] = (&ral[j].x)[0]; sA[1][o+1] = (&ral[j].x)[1];
                sA[1][o+2] = (&ral[j].x)[2]; sA[1][o+3] = (&ral[j].x)[3];
            }
        }
        #pragma unroll
        for (int pl = 0; pl < 2; pl++) {
            int o = brow*17 + bf4*4;
            sB[pl][o+0] = (&rbv[pl].x)[0]; sB[pl][o+1] = (&rbv[pl].x)[1];
            sB[pl][o+2] = (&rbv[pl].x)[2]; sB[pl][o+3] = (&rbv[pl].x)[3];
        }
        __syncthreads();
        if (c < 7) {
            int cc = (c+1)*16;
            #pragma unroll
            for (int j = 0; j < 2; j++)
                rah[j] = *(const uint4*)&Ah[(size_t)(m0 + arow[j])*128 + cc + af4[j]*4];
            if (p3) {
                #pragma unroll
                for (int j = 0; j < 2; j++)
                    ral[j] = *(const uint4*)&Al[(size_t)(m0 + arow[j])*128 + cc + af4[j]*4];
            }
            rbv[0] = *(const uint4*)&Wh[(size_t)(n0 + brow)*128 + cc + bf4*4];
            rbv[1] = *(const uint4*)&Wl[(size_t)(n0 + brow)*128 + cc + bf4*4];
        }
        #pragma unroll
        for (int kk = 0; kk < 2; kk++) {
            unsigned ah[2][4], al[2][4];
            #pragma unroll
            for (int mt = 0; mt < 2; mt++) {
                int b0 = (wm*32 + mt*16 + g)*17 + kk*8 + t;
                int b1 = b0 + 8*17;
                ah[mt][0] = sA[0][b0]; ah[mt][1] = sA[0][b1];
                ah[mt][2] = sA[0][b0+4]; ah[mt][3] = sA[0][b1+4];
                if (p3) {
                    al[mt][0] = sA[1][b0]; al[mt][1] = sA[1][b1];
                    al[mt][2] = sA[1][b0+4]; al[mt][3] = sA[1][b1+4];
                }
            }
            #pragma unroll
            for (int nt = 0; nt < 4; nt++) {
                int cb = (wn*32 + nt*8 + g)*17 + kk*8 + t;
                unsigned bh0 = sB[0][cb], bh1 = sB[0][cb+4];
                unsigned bl0 = sB[1][cb], bl1 = sB[1][cb+4];
                #pragma unroll
                for (int mt = 0; mt < 2; mt++) {
                    mmah(acc[mt][nt], ah[mt][0], ah[mt][1], ah[mt][2], ah[mt][3], bh0, bh1);
                    mmah(acc[mt][nt], ah[mt][0], ah[mt][1], ah[mt][2], ah[mt][3], bl0, bl1);
                    if (p3)
                        mmah(acc[mt][nt], al[mt][0], al[mt][1], al[mt][2], al[mt][3], bh0, bh1);
                }
            }
        }
        __syncthreads();
    }

    // epilogue
    #pragma unroll
    for (int mt = 0; mt < 2; mt++) {
        int row0 = m0 + wm*32 + mt*16 + g;
        int row1 = row0 + 8;
        #pragma unroll
        for (int nt = 0; nt < 4; nt++) {
            int col = n0 + wn*32 + nt*8 + t*2;
            int cp  = col >> 1;
            float bv0 = bias[col], bv1 = bias[col+1];
            float v00 = acc[mt][nt][0] + bv0, v01 = acc[mt][nt][1] + bv1;
            float v10 = acc[mt][nt][2] + bv0, v11 = acc[mt][nt][3] + bv1;
            if (op == 0) {
                g_qph[row0*128 + cp] = pkh(v00, v01);
                g_qph[row1*128 + cp] = pkh(v10, v11);
            } else if (op == 2) {
                g_vph[row0*128 + cp] = pkh(v00, v01);
                g_vph[row1*128 + cp] = pkh(v10, v11);
            } else if (op == 1) {
                unsigned hi, lo;
                split_pack(v00, v01, hi, lo);
                g_kph[row0*128 + cp] = hi;  g_kpl[row0*128 + cp] = lo;
                split_pack(v10, v11, hi, lo);
                g_kph[row1*128 + cp] = hi;  g_kpl[row1*128 + cp] = lo;
            } else if (op == 3 || op == 5) {
                float* dst = (op == 3) ? g_gate0 : g_mlp;
                v00 = 1.f/(1.f + __expf(-v00)); v01 = 1.f/(1.f + __expf(-v01));
                v10 = 1.f/(1.f + __expf(-v10)); v11 = 1.f/(1.f + __expf(-v11));
                *(float2*)&dst[(size_t)row0*EE + col] = make_float2(v00, v01);
                *(float2*)&dst[(size_t)row1*EE + col] = make_float2(v10, v11);
            } else {  // op 4
                size_t i0 = (size_t)row0*EE + col, i1 = (size_t)row1*EE + col;
                float2 ga0 = *(const float2*)&g_gate0[i0];
                float2 ga1 = *(const float2*)&g_gate0[i1];
                float2 mx0 = *(const float2*)&Matrix[i0];
                float2 mx1 = *(const float2*)&Matrix[i1];
                v00 = ga0.x*v00 + mx0.x;  v01 = ga0.y*v01 + mx0.y;
                v10 = ga1.x*v10 + mx1.x;  v11 = ga1.y*v11 + mx1.y;
                *(float2*)&g_gate1[i0] = make_float2(v00, v01);
                *(float2*)&g_gate1[i1] = make_float2(v10, v11);
                unsigned hi, lo;
                split_pack(v00, v01, hi, lo);
                g_g1h[row0*128 + cp] = hi;  g_g1l[row0*128 + cp] = lo;
                split_pack(v10, v11, hi, lo);
                g_g1h[row1*128 + cp] = hi;  g_g1l[row1*128 + cp] = lo;
            }
        }
    }
}

// ---------------- V repack: [row][dh-pair] -> [d][kv-pair] ------------------
__global__ __launch_bounds__(256) void vrepack()
{
    __shared__ unsigned s[128*17];
    int bh = blockIdx.x, b = bh >> 3, hd = bh & 7;
    int k0 = blockIdx.y * 128;
    int tid = threadIdx.x;
    for (int i = tid; i < 2048; i += 256) {
        int r = i >> 4, dp = i & 15;
        s[r*17 + dp] = g_vph[(size_t)(b*SS + k0 + r)*128 + hd*16 + dp];
    }
    __syncthreads();
    for (int i = tid; i < 2048; i += 256) {
        int kp = i & 63, d = i >> 6;
        unsigned sel = (d & 1) ? 0x7632u : 0x5410u;
        unsigned u0 = s[(2*kp)*17 + (d >> 1)];
        unsigned u1 = s[(2*kp+1)*17 + (d >> 1)];
        g_vth[(size_t)(bh*32 + d)*512 + k0/2 + kp] = __byte_perm(u0, u1, sel);
    }
}

// ---------------- fp16 tensor-core flash attention --------------------------
// grid (B*H, S/64), block 128 (4 warps), warp = 16 q rows, kv tile 64.
// QK: 2-pass qh*(kh+kl); PV: 1-pass fp16.
__global__ __launch_bounds__(128) void attn_h(
    const float* __restrict__ rb)
{
    __shared__ unsigned sKh[64*17], sKl[64*17];
    __shared__ unsigned sVh[32*36];
    __shared__ unsigned sP[64*36];

    int tid = threadIdx.x, lane = tid & 31, wq = tid >> 5;
    int g = lane >> 2, t = lane & 3, t2 = t*2;
    int bh = blockIdx.x, b = bh >> 3, hd = bh & 7;
    int q0 = blockIdx.y * 64;
    const float scale = 0.17677669529663687f;

    int r0 = q0 + wq*16 + g;
    int qrow0 = b*SS + r0, qrow1 = qrow0 + 8;

    unsigned qhf[2][4];
    #pragma unroll
    for (int kk = 0; kk < 2; kk++) {
        int b0 = qrow0*128 + hd*16 + kk*8 + t;
        int b1 = qrow1*128 + hd*16 + kk*8 + t;
        qhf[kk][0] = g_qph[b0]; qhf[kk][1] = g_qph[b1];
        qhf[kk][2] = g_qph[b0+4]; qhf[kk][3] = g_qph[b1+4];
    }

    float O[4][4];
    #pragma unroll
    for (int dn = 0; dn < 4; dn++)
        #pragma unroll
        for (int i = 0; i < 4; i++) O[dn][i] = 0.f;
    float m0s = -1e30f, m1s = -1e30f, l0s = 0.f, l1s = 0.f;

    for (int k0 = 0; k0 < SS; k0 += 64) {
        // K tiles [64][16 pairs] hi+lo
        #pragma unroll
        for (int j = 0; j < 2; j++) {
            int idx = tid + j*128;
            int r = idx >> 2, f4 = idx & 3;
            size_t ga = (size_t)(b*SS + k0 + r)*128 + hd*16 + f4*4;
            uint4 vh = *(const uint4*)&g_kph[ga];
            uint4 vl = *(const uint4*)&g_kpl[ga];
            int o = r*17 + f4*4;
            sKh[o]=vh.x; sKh[o+1]=vh.y; sKh[o+2]=vh.z; sKh[o+3]=vh.w;
            sKl[o]=vl.x; sKl[o+1]=vl.y; sKl[o+2]=vl.z; sKl[o+3]=vl.w;
        }
        // V tile [32 d][32 kv-pairs]
        #pragma unroll
        for (int j = 0; j < 2; j++) {
            int idx = tid + j*128;
            int d = idx >> 3, f4 = idx & 7;
            *(uint4*)&sVh[d*36 + f4*4] =
                *(const uint4*)&g_vth[(size_t)(bh*32 + d)*512 + k0/2 + f4*4];
        }
        __syncthreads();

        float S_[8][4];
        #pragma unroll
        for (int nt = 0; nt < 8; nt++)
            #pragma unroll
            for (int i = 0; i < 4; i++) S_[nt][i] = 0.f;
        #pragma unroll
        for (int kk = 0; kk < 2; kk++) {
            #pragma unroll
            for (int nt = 0; nt < 8; nt++) {
                int cb = (nt*8 + g)*17 + kk*8 + t;
                unsigned kh0 = sKh[cb], kh1 = sKh[cb+4];
                unsigned kl0 = sKl[cb], kl1 = sKl[cb+4];
                mmah(S_[nt], qhf[kk][0], qhf[kk][1], qhf[kk][2], qhf[kk][3], kh0, kh1);
                mmah(S_[nt], qhf[kk][0], qhf[kk][1], qhf[kk][2], qhf[kk][3], kl0, kl1);
            }
        }
        #pragma unroll
        for (int nt = 0; nt < 8; nt++) {
            const float* bp = &rb[(size_t)r0*SS + k0 + nt*8 + t2];
            float2 b0v = *(const float2*)bp;
            float2 b1v = *(const float2*)(bp + (size_t)8*SS);
            S_[nt][0] = S_[nt][0]*scale + b0v.x;
            S_[nt][1] = S_[nt][1]*scale + b0v.y;
            S_[nt][2] = S_[nt][2]*scale + b1v.x;
            S_[nt][3] = S_[nt][3]*scale + b1v.y;
        }

        float tm0 = -1e30f, tm1 = -1e30f;
        #pragma unroll
        for (int nt = 0; nt < 8; nt++) {
            tm0 = fmaxf(tm0, fmaxf(S_[nt][0], S_[nt][1]));
            tm1 = fmaxf(tm1, fmaxf(S_[nt][2], S_[nt][3]));
        }
        tm0 = fmaxf(tm0, __shfl_xor_sync(0xffffffffu, tm0, 1));
        tm0 = fmaxf(tm0, __shfl_xor_sync(0xffffffffu, tm0, 2));
        tm1 = fmaxf(tm1, __shfl_xor_sync(0xffffffffu, tm1, 1));
        tm1 = fmaxf(tm1, __shfl_xor_sync(0xffffffffu, tm1, 2));
        float nm0 = fmaxf(m0s, tm0), nm1 = fmaxf(m1s, tm1);
        float sc0 = __expf(m0s - nm0), sc1 = __expf(m1s - nm1);
        float rs0 = 0.f, rs1 = 0.f;
        int pr0 = (wq*16 + g)*36, pr1 = pr0 + 8*36;
        #pragma unroll
        for (int nt = 0; nt < 8; nt++) {
            float p0 = __expf(S_[nt][0] - nm0);
            float p1 = __expf(S_[nt][1] - nm0);
            float p2 = __expf(S_[nt][2] - nm1);
            float p3 = __expf(S_[nt][3] - nm1);
            rs0 += p0 + p1;  rs1 += p2 + p3;
            sP[pr0 + nt*4 + t] = pkh(p0, p1);
            sP[pr1 + nt*4 + t] = pkh(p2, p3);
        }
        rs0 += __shfl_xor_sync(0xffffffffu, rs0, 1);
        rs0 += __shfl_xor_sync(0xffffffffu, rs0, 2);
        rs1 += __shfl_xor_sync(0xffffffffu, rs1, 1);
        rs1 += __shfl_xor_sync(0xffffffffu, rs1, 2);
        l0s = l0s*sc0 + rs0;
        l1s = l1s*sc1 + rs1;
        m0s = nm0;  m1s = nm1;
        #pragma unroll
        for (int dn = 0; dn < 4; dn++) {
            O[dn][0] *= sc0; O[dn][1] *= sc0;
            O[dn][2] *= sc1; O[dn][3] *= sc1;
        }
        __syncwarp();

        // O += P @ V (1 pass)
        #pragma unroll
        for (int kk = 0; kk < 4; kk++) {
            int pa = pr0 + kk*8 + t;
            unsigned a0 = sP[pa], a1 = sP[pa + 8*36];
            unsigned a2 = sP[pa+4], a3 = sP[pa + 8*36 + 4];
            #pragma unroll
            for (int dn = 0; dn < 4; dn++) {
                int vb = (dn*8 + g)*36 + kk*8 + t;
                mmah(O[dn], a0, a1, a2, a3, sVh[vb], sVh[vb+4]);
            }
        }
        __syncthreads();
    }

    float il0 = 1.f/l0s, il1 = 1.f/l1s;
    #pragma unroll
    for (int dn = 0; dn < 4; dn++) {
        int cp = hd*16 + dn*4 + t;
        unsigned hi, lo;
        split_pack(O[dn][0]*il0, O[dn][1]*il0, hi, lo);
        g_oph[qrow0*128 + cp] = hi;  g_opl[qrow0*128 + cp] = lo;
        split_pack(O[dn][2]*il1, O[dn][3]*il1, hi, lo);
        g_oph[qrow1*128 + cp] = hi;  g_opl[qrow1*128 + cp] = lo;
    }
}

// ---------------- launch ----------------------------------------------------
extern "C" void kernel_launch(void* const* d_in, const int* in_sizes, int n_in,
                              void* d_out, int out_size)
{
    const float* Matrix = (const float*)d_in[0];
    const float* ln_g   = (const float*)d_in[1];
    const float* ln_b   = (const float*)d_in[2];
    const float* Wq     = (const float*)d_in[3];
    const float* bq     = (const float*)d_in[4];
    const float* Wk     = (const float*)d_in[5];
    const float* bk     = (const float*)d_in[6];
    const float* Wv     = (const float*)d_in[7];
    const float* bv     = (const float*)d_in[8];
    const float* Wo     = (const float*)d_in[9];
    const float* bo     = (const float*)d_in[10];
    const float* rel    = (const float*)d_in[11];
    const float* gW     = (const float*)d_in[12];
    const float* gb     = (const float*)d_in[13];
    const float* mW     = (const float*)d_in[14];
    const float* mb     = (const float*)d_in[15];
    float* out = (float*)d_out;

    wsplit<<<dim3(4,4,6), 256>>>(Wq, Wk, Wv, gW, Wo, mW);
    ln_kernel<<<MROWS/8, 256>>>(Matrix, ln_g, ln_b);

    // fused QKV + gate0
    gemm_h<<<dim3(4,128,4), 256>>>(bq, bk, bv, gb, bo, mb, Matrix, 0);

    vrepack<<<dim3(128,8), 256>>>();
    attn_h<<<dim3(BB*HH, SS/64), 128>>>(rel);

    gemm_h<<<dim3(4,128,1), 256>>>(bq, bk, bv, gb, bo, mb, Matrix, 4);
    gemm_h<<<dim3(4,128,1), 256>>>(bq, bk, bv, gb, bo, mb, Matrix, 5);

    final_kernel<<<MROWS/8, 256>>>(ln_g, ln_b, out);
}

// round 5
// speedup vs baseline: 2.6349x; 1.0887x over previous
#include <cuda_runtime.h>
#include <cuda_fp16.h>
#include <math.h>

#define BB 16
#define SS 1024
#define EE 256
#define HH 8
#define DHD 32
#define MROWS (BB*SS)   // 16384

// ---------------- scratch (static device arrays; no allocation allowed) ----
// packed fp16 planes: uint = (h16 even-k | h16 odd-k << 16)
__device__ unsigned g_wt[6][2][256*128];     // weight planes [n][kpair] hi/lo
__device__ unsigned g_rbh[SS*512];           // rel_bias fp16 pairs
__device__ unsigned g_lnh[MROWS*128];
__device__ unsigned g_mth[MROWS*128];
__device__ unsigned g_qph[MROWS*128];
__device__ unsigned g_kph[MROWS*128];
__device__ unsigned g_vph[MROWS*128];
__device__ unsigned g_vth[BB*HH*DHD*512];    // [bh*32+d][S/2] transposed V hi
__device__ unsigned g_oph[MROWS*128], g_opl[MROWS*128];
__device__ unsigned g_g1h[MROWS*128], g_g1l[MROWS*128];
__device__ float g_gate0[MROWS*EE], g_gate1[MROWS*EE], g_mlp[MROWS*EE];

// ---------------- helpers ---------------------------------------------------
__device__ __forceinline__ unsigned pkh(float a, float b) {
    __half2 t = __floats2half2_rn(a, b);
    return *reinterpret_cast<unsigned*>(&t);
}
__device__ __forceinline__ void split_pack(float a, float b, unsigned &hi, unsigned &lo) {
    __half ah = __float2half_rn(a);
    __half bh = __float2half_rn(b);
    float ar = a - __half2float(ah);
    float br = b - __half2float(bh);
    __half2 H = __halves2half2(ah, bh);
    __half2 L = __floats2half2_rn(ar, br);
    hi = *reinterpret_cast<unsigned*>(&H);
    lo = *reinterpret_cast<unsigned*>(&L);
}

// mma.sync m16n8k16 row.col f32 += f16 * f16
__device__ __forceinline__ void mmah(float* c,
    unsigned a0, unsigned a1, unsigned a2, unsigned a3,
    unsigned b0, unsigned b1)
{
    asm volatile(
        "mma.sync.aligned.m16n8k16.row.col.f32.f16.f16.f32 "
        "{%0,%1,%2,%3},{%4,%5,%6,%7},{%8,%9},{%0,%1,%2,%3};"
        : "+f"(c[0]), "+f"(c[1]), "+f"(c[2]), "+f"(c[3])
        : "r"(a0), "r"(a1), "r"(a2), "r"(a3), "r"(b0), "r"(b1));
}

// ---------------- weight split: W[256][256] -> [n][kpair] hi/lo planes -----
__global__ __launch_bounds__(256) void wsplit(
    const float* __restrict__ Wq, const float* __restrict__ Wk,
    const float* __restrict__ Wv, const float* __restrict__ gW,
    const float* __restrict__ Wo, const float* __restrict__ mW)
{
    const float* W;
    switch (blockIdx.z) {
        case 0: W = Wq; break; case 1: W = Wk; break; case 2: W = Wv; break;
        case 3: W = gW; break; case 4: W = Wo; break; default: W = mW; break;
    }
    __shared__ float s[64][65];
    int k0 = blockIdx.y * 64, n0 = blockIdx.x * 64;
    int tid = threadIdx.x;
    for (int i = tid; i < 4096; i += 256) {
        int r = i >> 6, c = i & 63;
        s[r][c] = W[(size_t)(k0 + r)*EE + n0 + c];
    }
    __syncthreads();
    for (int i = tid; i < 2048; i += 256) {
        int n = i >> 5, kp = i & 31;
        unsigned hi, lo;
        split_pack(s[2*kp][n], s[2*kp+1][n], hi, lo);
        int o = (n0 + n)*128 + k0/2 + kp;
        g_wt[blockIdx.z][0][o] = hi;
        g_wt[blockIdx.z][1][o] = lo;
    }
}

// ---------------- rel_bias -> fp16 pairs ------------------------------------
__global__ __launch_bounds__(256) void bsplit(const float* __restrict__ rel)
{
    int row = blockIdx.x, tid = threadIdx.x;
    #pragma unroll
    for (int j = 0; j < 2; j++) {
        int i = tid + j*256;
        float2 v = *(const float2*)&rel[(size_t)row*SS + 2*i];
        g_rbh[row*512 + i] = pkh(v.x, v.y);
    }
}

// ---------------- warp reductions -------------------------------------------
__device__ __forceinline__ float wsum(float v) {
    #pragma unroll
    for (int o = 16; o > 0; o >>= 1) v += __shfl_xor_sync(0xffffffffu, v, o);
    return v;
}

// ---------------- LN of input -> ln hi plane + Matrix hi plane --------------
__global__ __launch_bounds__(256) void ln_kernel(
    const float* __restrict__ x, const float* __restrict__ g,
    const float* __restrict__ b)
{
    int warp = threadIdx.x >> 5, lane = threadIdx.x & 31;
    int row = blockIdx.x*8 + warp;
    const float* xr = x + (size_t)row*EE + lane*8;
    float4 a0 = *(const float4*)xr;
    float4 a1 = *(const float4*)(xr + 4);
    float xv[8] = {a0.x,a0.y,a0.z,a0.w,a1.x,a1.y,a1.z,a1.w};
    float s = 0.f;
    #pragma unroll
    for (int i = 0; i < 8; i++) s += xv[i];
    float mean = wsum(s) * (1.f/EE);
    float vs = 0.f;
    #pragma unroll
    for (int i = 0; i < 8; i++) { float d = xv[i]-mean; vs += d*d; }
    float rstd = rsqrtf(wsum(vs)*(1.f/EE) + 1e-5f);
    float4 g0 = *(const float4*)(g + lane*8);
    float4 g1 = *(const float4*)(g + lane*8 + 4);
    float4 b0 = *(const float4*)(b + lane*8);
    float4 b1 = *(const float4*)(b + lane*8 + 4);
    float gg[8] = {g0.x,g0.y,g0.z,g0.w,g1.x,g1.y,g1.z,g1.w};
    float bb[8] = {b0.x,b0.y,b0.z,b0.w,b1.x,b1.y,b1.z,b1.w};
    float ln[8];
    #pragma unroll
    for (int i = 0; i < 8; i++) ln[i] = (xv[i]-mean)*rstd*gg[i] + bb[i];
    uint4 u, um;
    u.x = pkh(ln[0],ln[1]); u.y = pkh(ln[2],ln[3]);
    u.z = pkh(ln[4],ln[5]); u.w = pkh(ln[6],ln[7]);
    um.x = pkh(xv[0],xv[1]); um.y = pkh(xv[2],xv[3]);
    um.z = pkh(xv[4],xv[5]); um.w = pkh(xv[6],xv[7]);
    *(uint4*)&g_lnh[row*128 + lane*4] = u;
    *(uint4*)&g_mth[row*128 + lane*4] = um;
}

// ---------------- final: out = gate1 * LN(mlp) + gate1 ----------------------
__global__ __launch_bounds__(256) void final_kernel(
    const float* __restrict__ g, const float* __restrict__ b,
    float* __restrict__ out)
{
    int warp = threadIdx.x >> 5, lane = threadIdx.x & 31;
    int row = blockIdx.x*8 + warp;
    const float* mr = g_mlp + (size_t)row*EE + lane*8;
    float4 a0 = *(const float4*)mr;
    float4 a1 = *(const float4*)(mr + 4);
    float xv[8] = {a0.x,a0.y,a0.z,a0.w,a1.x,a1.y,a1.z,a1.w};
    float s = 0.f;
    #pragma unroll
    for (int i = 0; i < 8; i++) s += xv[i];
    float mean = wsum(s) * (1.f/EE);
    float vs = 0.f;
    #pragma unroll
    for (int i = 0; i < 8; i++) { float d = xv[i]-mean; vs += d*d; }
    float rstd = rsqrtf(wsum(vs)*(1.f/EE) + 1e-5f);
    float4 g0 = *(const float4*)(g + lane*8);
    float4 g1v = *(const float4*)(g + lane*8 + 4);
    float4 b0 = *(const float4*)(b + lane*8);
    float4 b1 = *(const float4*)(b + lane*8 + 4);
    float gg[8] = {g0.x,g0.y,g0.z,g0.w,g1v.x,g1v.y,g1v.z,g1v.w};
    float bb[8] = {b0.x,b0.y,b0.z,b0.w,b1.x,b1.y,b1.z,b1.w};
    const float* gr = g_gate1 + (size_t)row*EE + lane*8;
    float4 q0 = *(const float4*)gr;
    float4 q1 = *(const float4*)(gr + 4);
    float gv[8] = {q0.x,q0.y,q0.z,q0.w,q1.x,q1.y,q1.z,q1.w};
    float o[8];
    #pragma unroll
    for (int i = 0; i < 8; i++) {
        float lnm = (xv[i]-mean)*rstd*gg[i] + bb[i];
        o[i] = gv[i]*lnm + gv[i];
    }
    float* orow = out + (size_t)row*EE + lane*8;
    *(float4*)orow       = make_float4(o[0],o[1],o[2],o[3]);
    *(float4*)(orow + 4) = make_float4(o[4],o[5],o[6],o[7]);
}

// ---------------- fp16 tensor-core GEMM -------------------------------------
// C[M,256]=A[M,256]@W[256,256]; block 128x64, 8 warps, warp 32x32.
// np: ops 0..3 -> 1 pass (ah*bh); op 4,5 -> 3 passes (+ ah*bl + al*bh).
__global__ __launch_bounds__(256) void gemm_h(
    const float* __restrict__ bq, const float* __restrict__ bk,
    const float* __restrict__ bv, const float* __restrict__ gb,
    const float* __restrict__ bo, const float* __restrict__ mb,
    const float* __restrict__ Matrix, int op_base)
{
    int op = op_base + blockIdx.z;
    const unsigned *Ah, *Al = nullptr;
    const float* bias;
    switch (op) {
        case 0: Ah = g_lnh; bias = bq; break;
        case 1: Ah = g_lnh; bias = bk; break;
        case 2: Ah = g_lnh; bias = bv; break;
        case 3: Ah = g_mth; bias = gb; break;
        case 4: Ah = g_oph; Al = g_opl; bias = bo; break;
        default: Ah = g_g1h; Al = g_g1l; bias = mb; break;
    }
    bool p3 = (op >= 4);   // 3-pass for Wo / mW, 1-pass otherwise
    const unsigned* Wh = g_wt[op][0];
    const unsigned* Wl = g_wt[op][1];

    __shared__ unsigned sA[2][128*17];
    __shared__ unsigned sB[2][64*17];

    int tid = threadIdx.x, lane = tid & 31, warp = tid >> 5;
    int wm = warp >> 1, wn = warp & 1;
    int g = lane >> 2, t = lane & 3;
    int m0 = blockIdx.y * 128, n0 = blockIdx.x * 64;

    float acc[2][4][4];
    #pragma unroll
    for (int mt = 0; mt < 2; mt++)
        #pragma unroll
        for (int nt = 0; nt < 4; nt++)
            #pragma unroll
            for (int i = 0; i < 4; i++) acc[mt][nt][i] = 0.f;

    uint4 rah[2], ral[2], rbv[2];
    int arow[2], af4[2], brow, bf4;
    #pragma unroll
    for (int j = 0; j < 2; j++) { int idx = tid + j*256; arow[j] = idx >> 2; af4[j] = idx & 3; }
    brow = tid >> 2; bf4 = tid & 3;

    #pragma unroll 1
    for (int c = 0; c < 8; c++) {
        if (c == 0) {
            #pragma unroll
            for (int j = 0; j < 2; j++)
                rah[j] = *(const uint4*)&Ah[(size_t)(m0 + arow[j])*128 + af4[j]*4];
            rbv[0] = *(const uint4*)&Wh[(size_t)(n0 + brow)*128 + bf4*4];
            if (p3) {
                #pragma unroll
                for (int j = 0; j < 2; j++)
                    ral[j] = *(const uint4*)&Al[(size_t)(m0 + arow[j])*128 + af4[j]*4];
                rbv[1] = *(const uint4*)&Wl[(size_t)(n0 + brow)*128 + bf4*4];
            }
        }
        #pragma unroll
        for (int j = 0; j < 2; j++) {
            int o = arow[j]*17 + af4[j]*4;
            sA[0][o+0] = (&rah[j].x)[0]; sA[0][o+1] = (&rah[j].x)[1];
            sA[0][o+2] = (&rah[j].x)[2]; sA[0][o+3] = (&rah[j].x)[3];
        }
        {
            int o = brow*17 + bf4*4;
            sB[0][o+0] = (&rbv[0].x)[0]; sB[0][o+1] = (&rbv[0].x)[1];
            sB[0][o+2] = (&rbv[0].x)[2]; sB[0][o+3] = (&rbv[0].x)[3];
        }
        if (p3) {
            #pragma unroll
            for (int j = 0; j < 2; j++) {
                int o = arow[j]*17 + af4[j]*4;
                sA[1][o+0] = (&ral[j].x)[0]; sA[1][o+1] = (&ral[j].x)[1];
                sA[1][o+2] = (&ral[j].x)[2]; sA[1][o+3] = (&ral[j].x)[3];
            }
            int o = brow*17 + bf4*4;
            sB[1][o+0] = (&rbv[1].x)[0]; sB[1][o+1] = (&rbv[1].x)[1];
            sB[1][o+2] = (&rbv[1].x)[2]; sB[1][o+3] = (&rbv[1].x)[3];
        }
        __syncthreads();
        if (c < 7) {
            int cc = (c+1)*16;
            #pragma unroll
            for (int j = 0; j < 2; j++)
                rah[j] = *(const uint4*)&Ah[(size_t)(m0 + arow[j])*128 + cc + af4[j]*4];
            rbv[0] = *(const uint4*)&Wh[(size_t)(n0 + brow)*128 + cc + bf4*4];
            if (p3) {
                #pragma unroll
                for (int j = 0; j < 2; j++)
                    ral[j] = *(const uint4*)&Al[(size_t)(m0 + arow[j])*128 + cc + af4[j]*4];
                rbv[1] = *(const uint4*)&Wl[(size_t)(n0 + brow)*128 + cc + bf4*4];
            }
        }
        #pragma unroll
        for (int kk = 0; kk < 2; kk++) {
            unsigned ah[2][4], al[2][4];
            #pragma unroll
            for (int mt = 0; mt < 2; mt++) {
                int b0 = (wm*32 + mt*16 + g)*17 + kk*8 + t;
                int b1 = b0 + 8*17;
                ah[mt][0] = sA[0][b0]; ah[mt][1] = sA[0][b1];
                ah[mt][2] = sA[0][b0+4]; ah[mt][3] = sA[0][b1+4];
                if (p3) {
                    al[mt][0] = sA[1][b0]; al[mt][1] = sA[1][b1];
                    al[mt][2] = sA[1][b0+4]; al[mt][3] = sA[1][b1+4];
                }
            }
            #pragma unroll
            for (int nt = 0; nt < 4; nt++) {
                int cb = (wn*32 + nt*8 + g)*17 + kk*8 + t;
                unsigned bh0 = sB[0][cb], bh1 = sB[0][cb+4];
                #pragma unroll
                for (int mt = 0; mt < 2; mt++)
                    mmah(acc[mt][nt], ah[mt][0], ah[mt][1], ah[mt][2], ah[mt][3], bh0, bh1);
                if (p3) {
                    unsigned bl0 = sB[1][cb], bl1 = sB[1][cb+4];
                    #pragma unroll
                    for (int mt = 0; mt < 2; mt++) {
                        mmah(acc[mt][nt], ah[mt][0], ah[mt][1], ah[mt][2], ah[mt][3], bl0, bl1);
                        mmah(acc[mt][nt], al[mt][0], al[mt][1], al[mt][2], al[mt][3], bh0, bh1);
                    }
                }
            }
        }
        __syncthreads();
    }

    // epilogue
    #pragma unroll
    for (int mt = 0; mt < 2; mt++) {
        int row0 = m0 + wm*32 + mt*16 + g;
        int row1 = row0 + 8;
        #pragma unroll
        for (int nt = 0; nt < 4; nt++) {
            int col = n0 + wn*32 + nt*8 + t*2;
            int cp  = col >> 1;
            float bv0 = bias[col], bv1 = bias[col+1];
            float v00 = acc[mt][nt][0] + bv0, v01 = acc[mt][nt][1] + bv1;
            float v10 = acc[mt][nt][2] + bv0, v11 = acc[mt][nt][3] + bv1;
            if (op == 0) {
                g_qph[row0*128 + cp] = pkh(v00, v01);
                g_qph[row1*128 + cp] = pkh(v10, v11);
            } else if (op == 1) {
                g_kph[row0*128 + cp] = pkh(v00, v01);
                g_kph[row1*128 + cp] = pkh(v10, v11);
            } else if (op == 2) {
                g_vph[row0*128 + cp] = pkh(v00, v01);
                g_vph[row1*128 + cp] = pkh(v10, v11);
            } else if (op == 3 || op == 5) {
                float* dst = (op == 3) ? g_gate0 : g_mlp;
                v00 = 1.f/(1.f + __expf(-v00)); v01 = 1.f/(1.f + __expf(-v01));
                v10 = 1.f/(1.f + __expf(-v10)); v11 = 1.f/(1.f + __expf(-v11));
                *(float2*)&dst[(size_t)row0*EE + col] = make_float2(v00, v01);
                *(float2*)&dst[(size_t)row1*EE + col] = make_float2(v10, v11);
            } else {  // op 4
                size_t i0 = (size_t)row0*EE + col, i1 = (size_t)row1*EE + col;
                float2 ga0 = *(const float2*)&g_gate0[i0];
                float2 ga1 = *(const float2*)&g_gate0[i1];
                float2 mx0 = *(const float2*)&Matrix[i0];
                float2 mx1 = *(const float2*)&Matrix[i1];
                v00 = ga0.x*v00 + mx0.x;  v01 = ga0.y*v01 + mx0.y;
                v10 = ga1.x*v10 + mx1.x;  v11 = ga1.y*v11 + mx1.y;
                *(float2*)&g_gate1[i0] = make_float2(v00, v01);
                *(float2*)&g_gate1[i1] = make_float2(v10, v11);
                unsigned hi, lo;
                split_pack(v00, v01, hi, lo);
                g_g1h[row0*128 + cp] = hi;  g_g1l[row0*128 + cp] = lo;
                split_pack(v10, v11, hi, lo);
                g_g1h[row1*128 + cp] = hi;  g_g1l[row1*128 + cp] = lo;
            }
        }
    }
}

// ---------------- V repack: [row][dh-pair] -> [d][kv-pair] ------------------
__global__ __launch_bounds__(256) void vrepack()
{
    __shared__ unsigned s[128*17];
    int bh = blockIdx.x, b = bh >> 3, hd = bh & 7;
    int k0 = blockIdx.y * 128;
    int tid = threadIdx.x;
    for (int i = tid; i < 2048; i += 256) {
        int r = i >> 4, dp = i & 15;
        s[r*17 + dp] = g_vph[(size_t)(b*SS + k0 + r)*128 + hd*16 + dp];
    }
    __syncthreads();
    for (int i = tid; i < 2048; i += 256) {
        int kp = i & 63, d = i >> 6;
        unsigned sel = (d & 1) ? 0x7632u : 0x5410u;
        unsigned u0 = s[(2*kp)*17 + (d >> 1)];
        unsigned u1 = s[(2*kp+1)*17 + (d >> 1)];
        g_vth[(size_t)(bh*32 + d)*512 + k0/2 + kp] = __byte_perm(u0, u1, sel);
    }
}

// ---------------- fp16 tensor-core flash attention --------------------------
// grid (B*H, S/128), block 256 (8 warps), warp = 16 q rows, kv tile 64.
// QK: 1-pass; PV: 1-pass.
__global__ __launch_bounds__(256) void attn_h()
{
    __shared__ unsigned sKh[64*17];
    __shared__ unsigned sVh[32*36];
    __shared__ unsigned sP[128*36];

    int tid = threadIdx.x, lane = tid & 31, wq = tid >> 5;
    int g = lane >> 2, t = lane & 3;
    int bh = blockIdx.x, b = bh >> 3, hd = bh & 7;
    int q0 = blockIdx.y * 128;
    const float scale = 0.17677669529663687f;

    int r0 = q0 + wq*16 + g;
    int qrow0 = b*SS + r0, qrow1 = qrow0 + 8;

    unsigned qhf[2][4];
    #pragma unroll
    for (int kk = 0; kk < 2; kk++) {
        int b0 = qrow0*128 + hd*16 + kk*8 + t;
        int b1 = qrow1*128 + hd*16 + kk*8 + t;
        qhf[kk][0] = g_qph[b0]; qhf[kk][1] = g_qph[b1];
        qhf[kk][2] = g_qph[b0+4]; qhf[kk][3] = g_qph[b1+4];
    }

    float O[4][4];
    #pragma unroll
    for (int dn = 0; dn < 4; dn++)
        #pragma unroll
        for (int i = 0; i < 4; i++) O[dn][i] = 0.f;
    float m0s = -1e30f, m1s = -1e30f, l0s = 0.f, l1s = 0.f;

    for (int k0 = 0; k0 < SS; k0 += 64) {
        // K tile [64][16 pairs]: 1024 uints, 256 threads x uint4
        {
            int r = tid >> 2, f4 = tid & 3;
            uint4 vh = *(const uint4*)&g_kph[(size_t)(b*SS + k0 + r)*128 + hd*16 + f4*4];
            int o = r*17 + f4*4;
            sKh[o]=vh.x; sKh[o+1]=vh.y; sKh[o+2]=vh.z; sKh[o+3]=vh.w;
        }
        // V tile [32 d][32 kv-pairs]: 1024 uints
        {
            int d = tid >> 3, f4 = tid & 7;
            *(uint4*)&sVh[d*36 + f4*4] =
                *(const uint4*)&g_vth[(size_t)(bh*32 + d)*512 + k0/2 + f4*4];
        }
        __syncthreads();

        float S_[8][4];
        #pragma unroll
        for (int nt = 0; nt < 8; nt++)
            #pragma unroll
            for (int i = 0; i < 4; i++) S_[nt][i] = 0.f;
        #pragma unroll
        for (int kk = 0; kk < 2; kk++) {
            #pragma unroll
            for (int nt = 0; nt < 8; nt++) {
                int cb = (nt*8 + g)*17 + kk*8 + t;
                mmah(S_[nt], qhf[kk][0], qhf[kk][1], qhf[kk][2], qhf[kk][3],
                     sKh[cb], sKh[cb+4]);
            }
        }
        // add bias (fp16 pairs)
        #pragma unroll
        for (int nt = 0; nt < 8; nt++) {
            int pc = (k0 >> 1) + nt*4 + t;
            unsigned u0 = g_rbh[r0*512 + pc];
            unsigned u1 = g_rbh[(r0+8)*512 + pc];
            __half2 h0 = *reinterpret_cast<__half2*>(&u0);
            __half2 h1 = *reinterpret_cast<__half2*>(&u1);
            float2 b0v = __half22float2(h0);
            float2 b1v = __half22float2(h1);
            S_[nt][0] = S_[nt][0]*scale + b0v.x;
            S_[nt][1] = S_[nt][1]*scale + b0v.y;
            S_[nt][2] = S_[nt][2]*scale + b1v.x;
            S_[nt][3] = S_[nt][3]*scale + b1v.y;
        }

        float tm0 = -1e30f, tm1 = -1e30f;
        #pragma unroll
        for (int nt = 0; nt < 8; nt++) {
            tm0 = fmaxf(tm0, fmaxf(S_[nt][0], S_[nt][1]));
            tm1 = fmaxf(tm1, fmaxf(S_[nt][2], S_[nt][3]));
        }
        tm0 = fmaxf(tm0, __shfl_xor_sync(0xffffffffu, tm0, 1));
        tm0 = fmaxf(tm0, __shfl_xor_sync(0xffffffffu, tm0, 2));
        tm1 = fmaxf(tm1, __shfl_xor_sync(0xffffffffu, tm1, 1));
        tm1 = fmaxf(tm1, __shfl_xor_sync(0xffffffffu, tm1, 2));
        float nm0 = fmaxf(m0s, tm0), nm1 = fmaxf(m1s, tm1);
        float sc0 = __expf(m0s - nm0), sc1 = __expf(m1s - nm1);
        float rs0 = 0.f, rs1 = 0.f;
        int pr0 = (wq*16 + g)*36, pr1 = pr0 + 8*36;
        #pragma unroll
        for (int nt = 0; nt < 8; nt++) {
            float p0 = __expf(S_[nt][0] - nm0);
            float p1 = __expf(S_[nt][1] - nm0);
            float p2 = __expf(S_[nt][2] - nm1);
            float p3 = __expf(S_[nt][3] - nm1);
            rs0 += p0 + p1;  rs1 += p2 + p3;
            sP[pr0 + nt*4 + t] = pkh(p0, p1);
            sP[pr1 + nt*4 + t] = pkh(p2, p3);
        }
        rs0 += __shfl_xor_sync(0xffffffffu, rs0, 1);
        rs0 += __shfl_xor_sync(0xffffffffu, rs0, 2);
        rs1 += __shfl_xor_sync(0xffffffffu, rs1, 1);
        rs1 += __shfl_xor_sync(0xffffffffu, rs1, 2);
        l0s = l0s*sc0 + rs0;
        l1s = l1s*sc1 + rs1;
        m0s = nm0;  m1s = nm1;
        #pragma unroll
        for (int dn = 0; dn < 4; dn++) {
            O[dn][0] *= sc0; O[dn][1] *= sc0;
            O[dn][2] *= sc1; O[dn][3] *= sc1;
        }
        __syncwarp();

        // O += P @ V
        #pragma unroll
        for (int kk = 0; kk < 4; kk++) {
            int pa = pr0 + kk*8 + t;
            unsigned a0 = sP[pa], a1 = sP[pa + 8*36];
            unsigned a2 = sP[pa+4], a3 = sP[pa + 8*36 + 4];
            #pragma unroll
            for (int dn = 0; dn < 4; dn++) {
                int vb = (dn*8 + g)*36 + kk*8 + t;
                mmah(O[dn], a0, a1, a2, a3, sVh[vb], sVh[vb+4]);
            }
        }
        __syncthreads();
    }

    float il0 = 1.f/l0s, il1 = 1.f/l1s;
    #pragma unroll
    for (int dn = 0; dn < 4; dn++) {
        int cp = hd*16 + dn*4 + t;
        unsigned hi, lo;
        split_pack(O[dn][0]*il0, O[dn][1]*il0, hi, lo);
        g_oph[qrow0*128 + cp] = hi;  g_opl[qrow0*128 + cp] = lo;
        split_pack(O[dn][2]*il1, O[dn][3]*il1, hi, lo);
        g_oph[qrow1*128 + cp] = hi;  g_opl[qrow1*128 + cp] = lo;
    }
}

// ---------------- launch ----------------------------------------------------
extern "C" void kernel_launch(void* const* d_in, const int* in_sizes, int n_in,
                              void* d_out, int out_size)
{
    const float* Matrix = (const float*)d_in[0];
    const float* ln_g   = (const float*)d_in[1];
    const float* ln_b   = (const float*)d_in[2];
    const float* Wq     = (const float*)d_in[3];
    const float* bq     = (const float*)d_in[4];
    const float* Wk     = (const float*)d_in[5];
    const float* bk     = (const float*)d_in[6];
    const float* Wv     = (const float*)d_in[7];
    const float* bv     = (const float*)d_in[8];
    const float* Wo     = (const float*)d_in[9];
    const float* bo     = (const float*)d_in[10];
    const float* rel    = (const float*)d_in[11];
    const float* gW     = (const float*)d_in[12];
    const float* gb     = (const float*)d_in[13];
    const float* mW     = (const float*)d_in[14];
    const float* mb     = (const float*)d_in[15];
    float* out = (float*)d_out;

    wsplit<<<dim3(4,4,6), 256>>>(Wq, Wk, Wv, gW, Wo, mW);
    bsplit<<<SS, 256>>>(rel);
    ln_kernel<<<MROWS/8, 256>>>(Matrix, ln_g, ln_b);

    // fused QKV + gate0 (1-pass fp16)
    gemm_h<<<dim3(4,128,4), 256>>>(bq, bk, bv, gb, bo, mb, Matrix, 0);

    vrepack<<<dim3(128,8), 256>>>();
    attn_h<<<dim3(BB*HH, SS/128), 256>>>();

    gemm_h<<<dim3(4,128,1), 256>>>(bq, bk, bv, gb, bo, mb, Matrix, 4);
    gemm_h<<<dim3(4,128,1), 256>>>(bq, bk, bv, gb, bo, mb, Matrix, 5);

    final_kernel<<<MROWS/8, 256>>>(ln_g, ln_b, out);
}

// round 6
// speedup vs baseline: 3.5583x; 1.3504x over previous
#include <cuda_runtime.h>
#include <cuda_fp16.h>
#include <math.h>

#define BB 16
#define SS 1024
#define EE 256
#define HH 8
#define DHD 32
#define MROWS (BB*SS)   // 16384
#define GP 20           // smem pitch (uints): rows 80B apart -> 16B-aligned, LDSM conflict-free

// ---------------- scratch (static device arrays; no allocation allowed) ----
__device__ unsigned g_wt[6][2][256*128];     // weight planes [n][kpair] hi/lo
__device__ unsigned g_rbh[SS*512];           // rel_bias fp16 pairs
__device__ unsigned g_lnh[MROWS*128];
__device__ unsigned g_mth[MROWS*128];
__device__ unsigned g_qph[MROWS*128];        // pre-scaled by 1/sqrt(DH)
__device__ unsigned g_kph[MROWS*128];
__device__ unsigned g_vph[MROWS*128];
__device__ unsigned g_oph[MROWS*128];
__device__ unsigned g_g1h[MROWS*128];
__device__ float g_gate0[MROWS*EE], g_gate1[MROWS*EE], g_mlp[MROWS*EE];

// ---------------- helpers ---------------------------------------------------
__device__ __forceinline__ unsigned pkh(float a, float b) {
    __half2 t = __floats2half2_rn(a, b);
    return *reinterpret_cast<unsigned*>(&t);
}
__device__ __forceinline__ void split_pack(float a, float b, unsigned &hi, unsigned &lo) {
    __half ah = __float2half_rn(a);
    __half bh = __float2half_rn(b);
    float ar = a - __half2float(ah);
    float br = b - __half2float(bh);
    __half2 H = __halves2half2(ah, bh);
    __half2 L = __floats2half2_rn(ar, br);
    hi = *reinterpret_cast<unsigned*>(&H);
    lo = *reinterpret_cast<unsigned*>(&L);
}
__device__ __forceinline__ void mmah(float* c,
    unsigned a0, unsigned a1, unsigned a2, unsigned a3,
    unsigned b0, unsigned b1)
{
    asm volatile(
        "mma.sync.aligned.m16n8k16.row.col.f32.f16.f16.f32 "
        "{%0,%1,%2,%3},{%4,%5,%6,%7},{%8,%9},{%0,%1,%2,%3};"
        : "+f"(c[0]), "+f"(c[1]), "+f"(c[2]), "+f"(c[3])
        : "r"(a0), "r"(a1), "r"(a2), "r"(a3), "r"(b0), "r"(b1));
}
__device__ __forceinline__ void ldsm4(unsigned &r0, unsigned &r1, unsigned &r2, unsigned &r3, unsigned addr) {
    asm volatile("ldmatrix.sync.aligned.m8n8.x4.shared.b16 {%0,%1,%2,%3}, [%4];"
        : "=r"(r0), "=r"(r1), "=r"(r2), "=r"(r3) : "r"(addr));
}
__device__ __forceinline__ void ldsm4t(unsigned &r0, unsigned &r1, unsigned &r2, unsigned &r3, unsigned addr) {
    asm volatile("ldmatrix.sync.aligned.m8n8.x4.trans.shared.b16 {%0,%1,%2,%3}, [%4];"
        : "=r"(r0), "=r"(r1), "=r"(r2), "=r"(r3) : "r"(addr));
}

// ---------------- weight split ----------------------------------------------
__global__ __launch_bounds__(256) void wsplit(
    const float* __restrict__ Wq, const float* __restrict__ Wk,
    const float* __restrict__ Wv, const float* __restrict__ gW,
    const float* __restrict__ Wo, const float* __restrict__ mW)
{
    const float* W;
    switch (blockIdx.z) {
        case 0: W = Wq; break; case 1: W = Wk; break; case 2: W = Wv; break;
        case 3: W = gW; break; case 4: W = Wo; break; default: W = mW; break;
    }
    __shared__ float s[64][65];
    int k0 = blockIdx.y * 64, n0 = blockIdx.x * 64;
    int tid = threadIdx.x;
    for (int i = tid; i < 4096; i += 256) {
        int r = i >> 6, c = i & 63;
        s[r][c] = W[(size_t)(k0 + r)*EE + n0 + c];
    }
    __syncthreads();
    for (int i = tid; i < 2048; i += 256) {
        int n = i >> 5, kp = i & 31;
        unsigned hi, lo;
        split_pack(s[2*kp][n], s[2*kp+1][n], hi, lo);
        int o = (n0 + n)*128 + k0/2 + kp;
        g_wt[blockIdx.z][0][o] = hi;
        g_wt[blockIdx.z][1][o] = lo;
    }
}

// ---------------- rel_bias -> fp16 pairs ------------------------------------
__global__ __launch_bounds__(256) void bsplit(const float* __restrict__ rel)
{
    int row = blockIdx.x, tid = threadIdx.x;
    #pragma unroll
    for (int j = 0; j < 2; j++) {
        int i = tid + j*256;
        float2 v = *(const float2*)&rel[(size_t)row*SS + 2*i];
        g_rbh[row*512 + i] = pkh(v.x, v.y);
    }
}

__device__ __forceinline__ float wsum(float v) {
    #pragma unroll
    for (int o = 16; o > 0; o >>= 1) v += __shfl_xor_sync(0xffffffffu, v, o);
    return v;
}

// ---------------- LN of input -> ln hi plane + Matrix hi plane --------------
__global__ __launch_bounds__(256) void ln_kernel(
    const float* __restrict__ x, const float* __restrict__ g,
    const float* __restrict__ b)
{
    int warp = threadIdx.x >> 5, lane = threadIdx.x & 31;
    int row = blockIdx.x*8 + warp;
    const float* xr = x + (size_t)row*EE + lane*8;
    float4 a0 = *(const float4*)xr;
    float4 a1 = *(const float4*)(xr + 4);
    float xv[8] = {a0.x,a0.y,a0.z,a0.w,a1.x,a1.y,a1.z,a1.w};
    float s = 0.f;
    #pragma unroll
    for (int i = 0; i < 8; i++) s += xv[i];
    float mean = wsum(s) * (1.f/EE);
    float vs = 0.f;
    #pragma unroll
    for (int i = 0; i < 8; i++) { float d = xv[i]-mean; vs += d*d; }
    float rstd = rsqrtf(wsum(vs)*(1.f/EE) + 1e-5f);
    float4 g0 = *(const float4*)(g + lane*8);
    float4 g1 = *(const float4*)(g + lane*8 + 4);
    float4 b0 = *(const float4*)(b + lane*8);
    float4 b1 = *(const float4*)(b + lane*8 + 4);
    float gg[8] = {g0.x,g0.y,g0.z,g0.w,g1.x,g1.y,g1.z,g1.w};
    float bb[8] = {b0.x,b0.y,b0.z,b0.w,b1.x,b1.y,b1.z,b1.w};
    float ln[8];
    #pragma unroll
    for (int i = 0; i < 8; i++) ln[i] = (xv[i]-mean)*rstd*gg[i] + bb[i];
    uint4 u, um;
    u.x = pkh(ln[0],ln[1]); u.y = pkh(ln[2],ln[3]);
    u.z = pkh(ln[4],ln[5]); u.w = pkh(ln[6],ln[7]);
    um.x = pkh(xv[0],xv[1]); um.y = pkh(xv[2],xv[3]);
    um.z = pkh(xv[4],xv[5]); um.w = pkh(xv[6],xv[7]);
    *(uint4*)&g_lnh[row*128 + lane*4] = u;
    *(uint4*)&g_mth[row*128 + lane*4] = um;
}

// ---------------- final: out = gate1 * LN(mlp) + gate1 ----------------------
__global__ __launch_bounds__(256) void final_kernel(
    const float* __restrict__ g, const float* __restrict__ b,
    float* __restrict__ out)
{
    int warp = threadIdx.x >> 5, lane = threadIdx.x & 31;
    int row = blockIdx.x*8 + warp;
    const float* mr = g_mlp + (size_t)row*EE + lane*8;
    float4 a0 = *(const float4*)mr;
    float4 a1 = *(const float4*)(mr + 4);
    float xv[8] = {a0.x,a0.y,a0.z,a0.w,a1.x,a1.y,a1.z,a1.w};
    float s = 0.f;
    #pragma unroll
    for (int i = 0; i < 8; i++) s += xv[i];
    float mean = wsum(s) * (1.f/EE);
    float vs = 0.f;
    #pragma unroll
    for (int i = 0; i < 8; i++) { float d = xv[i]-mean; vs += d*d; }
    float rstd = rsqrtf(wsum(vs)*(1.f/EE) + 1e-5f);
    float4 g0 = *(const float4*)(g + lane*8);
    float4 g1v = *(const float4*)(g + lane*8 + 4);
    float4 b0 = *(const float4*)(b + lane*8);
    float4 b1 = *(const float4*)(b + lane*8 + 4);
    float gg[8] = {g0.x,g0.y,g0.z,g0.w,g1v.x,g1v.y,g1v.z,g1v.w};
    float bb[8] = {b0.x,b0.y,b0.z,b0.w,b1.x,b1.y,b1.z,b1.w};
    const float* gr = g_gate1 + (size_t)row*EE + lane*8;
    float4 q0 = *(const float4*)gr;
    float4 q1 = *(const float4*)(gr + 4);
    float gv[8] = {q0.x,q0.y,q0.z,q0.w,q1.x,q1.y,q1.z,q1.w};
    float o[8];
    #pragma unroll
    for (int i = 0; i < 8; i++) {
        float lnm = (xv[i]-mean)*rstd*gg[i] + bb[i];
        o[i] = gv[i]*lnm + gv[i];
    }
    float* orow = out + (size_t)row*EE + lane*8;
    *(float4*)orow       = make_float4(o[0],o[1],o[2],o[3]);
    *(float4*)(orow + 4) = make_float4(o[4],o[5],o[6],o[7]);
}

// ---------------- fp16 tensor-core GEMM (ldmatrix) --------------------------
// C[M,256]=A[M,256]@W[256,256]; block 128x64, 8 warps (4m x 2n), warp 32x32.
// ops 0..3: 1-pass (ah*bh); ops 4,5: 2-pass (ah*bh + ah*bl).
__global__ __launch_bounds__(256) void gemm_h(
    const float* __restrict__ bq, const float* __restrict__ bk,
    const float* __restrict__ bv, const float* __restrict__ gb,
    const float* __restrict__ bo, const float* __restrict__ mb,
    const float* __restrict__ Matrix, int op_base)
{
    int op = op_base + blockIdx.z;
    const unsigned* Ah;
    const float* bias;
    switch (op) {
        case 0: Ah = g_lnh; bias = bq; break;
        case 1: Ah = g_lnh; bias = bk; break;
        case 2: Ah = g_lnh; bias = bv; break;
        case 3: Ah = g_mth; bias = gb; break;
        case 4: Ah = g_oph; bias = bo; break;
        default: Ah = g_g1h; bias = mb; break;
    }
    bool p2 = (op >= 4);
    const unsigned* Wh = g_wt[op][0];
    const unsigned* Wl = g_wt[op][1];

    __shared__ __align__(16) unsigned sA[128*GP];
    __shared__ __align__(16) unsigned sB[2][64*GP];

    int tid = threadIdx.x, lane = tid & 31, warp = tid >> 5;
    int wm = warp >> 1, wn = warp & 1;
    int g = lane >> 2, t = lane & 3;
    int m0 = blockIdx.y * 128, n0 = blockIdx.x * 64;

    unsigned sA_u = (unsigned)__cvta_generic_to_shared(sA);
    unsigned sB0_u = (unsigned)__cvta_generic_to_shared(sB[0]);
    unsigned sB1_u = (unsigned)__cvta_generic_to_shared(sB[1]);

    // LDSM per-lane address bases
    int l16 = lane & 15, secA = lane >> 4;
    unsigned aBase = sA_u + (((wm*32 + l16)*GP) + secA*4)*4;  // + mt*1280 + kk*32
    int l8 = lane & 7, qd = lane >> 3;
    unsigned bBase = (((wn*32 + (qd>>1)*8 + l8)*GP) + (qd&1)*4)*4;  // + p*1280 + kk*32

    float acc[2][4][4];
    #pragma unroll
    for (int mt = 0; mt < 2; mt++)
        #pragma unroll
        for (int nt = 0; nt < 4; nt++)
            #pragma unroll
            for (int i = 0; i < 4; i++) acc[mt][nt][i] = 0.f;

    uint4 rah[2], rbv[2];
    int arow[2], af4[2], brow, bf4;
    #pragma unroll
    for (int j = 0; j < 2; j++) { int idx = tid + j*256; arow[j] = idx >> 2; af4[j] = idx & 3; }
    brow = tid >> 2; bf4 = tid & 3;

    #pragma unroll 1
    for (int c = 0; c < 8; c++) {
        if (c == 0) {
            #pragma unroll
            for (int j = 0; j < 2; j++)
                rah[j] = *(const uint4*)&Ah[(size_t)(m0 + arow[j])*128 + af4[j]*4];
            rbv[0] = *(const uint4*)&Wh[(size_t)(n0 + brow)*128 + bf4*4];
            if (p2) rbv[1] = *(const uint4*)&Wl[(size_t)(n0 + brow)*128 + bf4*4];
        }
        #pragma unroll
        for (int j = 0; j < 2; j++)
            *(uint4*)&sA[arow[j]*GP + af4[j]*4] = rah[j];
        *(uint4*)&sB[0][brow*GP + bf4*4] = rbv[0];
        if (p2) *(uint4*)&sB[1][brow*GP + bf4*4] = rbv[1];
        __syncthreads();
        if (c < 7) {
            int cc = (c+1)*16;
            #pragma unroll
            for (int j = 0; j < 2; j++)
                rah[j] = *(const uint4*)&Ah[(size_t)(m0 + arow[j])*128 + cc + af4[j]*4];
            rbv[0] = *(const uint4*)&Wh[(size_t)(n0 + brow)*128 + cc + bf4*4];
            if (p2) rbv[1] = *(const uint4*)&Wl[(size_t)(n0 + brow)*128 + cc + bf4*4];
        }
        #pragma unroll
        for (int kk = 0; kk < 2; kk++) {
            unsigned a[2][4];
            #pragma unroll
            for (int mt = 0; mt < 2; mt++)
                ldsm4(a[mt][0], a[mt][1], a[mt][2], a[mt][3], aBase + mt*1280 + kk*32);
            #pragma unroll
            for (int p = 0; p < 2; p++) {
                unsigned bh0, bh1, bh2, bh3;
                ldsm4(bh0, bh1, bh2, bh3, sB0_u + bBase + p*1280 + kk*32);
                #pragma unroll
                for (int mt = 0; mt < 2; mt++) {
                    mmah(acc[mt][2*p  ], a[mt][0], a[mt][1], a[mt][2], a[mt][3], bh0, bh1);
                    mmah(acc[mt][2*p+1], a[mt][0], a[mt][1], a[mt][2], a[mt][3], bh2, bh3);
                }
                if (p2) {
                    unsigned bl0, bl1, bl2, bl3;
                    ldsm4(bl0, bl1, bl2, bl3, sB1_u + bBase + p*1280 + kk*32);
                    #pragma unroll
                    for (int mt = 0; mt < 2; mt++) {
                        mmah(acc[mt][2*p  ], a[mt][0], a[mt][1], a[mt][2], a[mt][3], bl0, bl1);
                        mmah(acc[mt][2*p+1], a[mt][0], a[mt][1], a[mt][2], a[mt][3], bl2, bl3);
                    }
                }
            }
        }
        __syncthreads();
    }

    const float qscale = 0.17677669529663687f;   // 1/sqrt(32)
    #pragma unroll
    for (int mt = 0; mt < 2; mt++) {
        int row0 = m0 + wm*32 + mt*16 + g;
        int row1 = row0 + 8;
        #pragma unroll
        for (int nt = 0; nt < 4; nt++) {
            int col = n0 + wn*32 + nt*8 + t*2;
            int cp  = col >> 1;
            float bv0 = bias[col], bv1 = bias[col+1];
            float v00 = acc[mt][nt][0] + bv0, v01 = acc[mt][nt][1] + bv1;
            float v10 = acc[mt][nt][2] + bv0, v11 = acc[mt][nt][3] + bv1;
            if (op == 0) {
                g_qph[row0*128 + cp] = pkh(v00*qscale, v01*qscale);
                g_qph[row1*128 + cp] = pkh(v10*qscale, v11*qscale);
            } else if (op == 1) {
                g_kph[row0*128 + cp] = pkh(v00, v01);
                g_kph[row1*128 + cp] = pkh(v10, v11);
            } else if (op == 2) {
                g_vph[row0*128 + cp] = pkh(v00, v01);
                g_vph[row1*128 + cp] = pkh(v10, v11);
            } else if (op == 3 || op == 5) {
                float* dst = (op == 3) ? g_gate0 : g_mlp;
                v00 = 1.f/(1.f + __expf(-v00)); v01 = 1.f/(1.f + __expf(-v01));
                v10 = 1.f/(1.f + __expf(-v10)); v11 = 1.f/(1.f + __expf(-v11));
                *(float2*)&dst[(size_t)row0*EE + col] = make_float2(v00, v01);
                *(float2*)&dst[(size_t)row1*EE + col] = make_float2(v10, v11);
            } else {  // op 4
                size_t i0 = (size_t)row0*EE + col, i1 = (size_t)row1*EE + col;
                float2 ga0 = *(const float2*)&g_gate0[i0];
                float2 ga1 = *(const float2*)&g_gate0[i1];
                float2 mx0 = *(const float2*)&Matrix[i0];
                float2 mx1 = *(const float2*)&Matrix[i1];
                v00 = ga0.x*v00 + mx0.x;  v01 = ga0.y*v01 + mx0.y;
                v10 = ga1.x*v10 + mx1.x;  v11 = ga1.y*v11 + mx1.y;
                *(float2*)&g_gate1[i0] = make_float2(v00, v01);
                *(float2*)&g_gate1[i1] = make_float2(v10, v11);
                g_g1h[row0*128 + cp] = pkh(v00, v01);
                g_g1h[row1*128 + cp] = pkh(v10, v11);
            }
        }
    }
}

// ---------------- fp16 flash attention (ldmatrix, P in registers) -----------
// grid (B*H, S/128), block 256 (8 warps), warp = 16 q rows, kv tile 64.
__global__ __launch_bounds__(256) void attn_h()
{
    __shared__ __align__(16) unsigned sK[64*GP];
    __shared__ __align__(16) unsigned sV[64*GP];

    int tid = threadIdx.x, lane = tid & 31, wq = tid >> 5;
    int g = lane >> 2, t = lane & 3;
    int bh = blockIdx.x, b = bh >> 3, hd = bh & 7;
    int q0 = blockIdx.y * 128;

    int r0 = q0 + wq*16 + g;
    int qrow0 = b*SS + r0, qrow1 = qrow0 + 8;

    unsigned sK_u = (unsigned)__cvta_generic_to_shared(sK);
    unsigned sV_u = (unsigned)__cvta_generic_to_shared(sV);
    int l8 = lane & 7, qd = lane >> 3;
    // K (non-trans): row = (p*2+(qd>>1))*8 + l8, col = kk*8 + (qd&1)*4
    unsigned kBase = sK_u + (((qd>>1)*8 + l8)*GP + (qd&1)*4)*4;   // + p*1280 + kk*32
    // V (trans): row = kk*16 + (qd&1)*8 + l8, col = (p*2+(qd>>1))*4
    unsigned vBase = sV_u + (((qd&1)*8 + l8)*GP)*4 + (qd>>1)*16;  // + kk*1280 + p*32

    unsigned qhf[2][4];
    #pragma unroll
    for (int kk = 0; kk < 2; kk++) {
        int b0 = qrow0*128 + hd*16 + kk*8 + t;
        int b1 = qrow1*128 + hd*16 + kk*8 + t;
        qhf[kk][0] = g_qph[b0]; qhf[kk][1] = g_qph[b1];
        qhf[kk][2] = g_qph[b0+4]; qhf[kk][3] = g_qph[b1+4];
    }

    float O[4][4];
    #pragma unroll
    for (int dn = 0; dn < 4; dn++)
        #pragma unroll
        for (int i = 0; i < 4; i++) O[dn][i] = 0.f;
    float m0s = -1e30f, m1s = -1e30f, l0s = 0.f, l1s = 0.f;

    int ldr = tid >> 2, ldf = tid & 3;

    for (int k0 = 0; k0 < SS; k0 += 64) {
        *(uint4*)&sK[ldr*GP + ldf*4] =
            *(const uint4*)&g_kph[(size_t)(b*SS + k0 + ldr)*128 + hd*16 + ldf*4];
        *(uint4*)&sV[ldr*GP + ldf*4] =
            *(const uint4*)&g_vph[(size_t)(b*SS + k0 + ldr)*128 + hd*16 + ldf*4];
        __syncthreads();

        // scores = q.k (q pre-scaled)
        float S_[8][4];
        #pragma unroll
        for (int nt = 0; nt < 8; nt++)
            #pragma unroll
            for (int i = 0; i < 4; i++) S_[nt][i] = 0.f;
        #pragma unroll
        for (int kk = 0; kk < 2; kk++) {
            #pragma unroll
            for (int p = 0; p < 4; p++) {
                unsigned k0r, k1r, k2r, k3r;
                ldsm4(k0r, k1r, k2r, k3r, kBase + p*1280 + kk*32);
                mmah(S_[2*p  ], qhf[kk][0], qhf[kk][1], qhf[kk][2], qhf[kk][3], k0r, k1r);
                mmah(S_[2*p+1], qhf[kk][0], qhf[kk][1], qhf[kk][2], qhf[kk][3], k2r, k3r);
            }
        }
        // add bias (fp16 pairs)
        #pragma unroll
        for (int nt = 0; nt < 8; nt++) {
            int pc = (k0 >> 1) + nt*4 + t;
            unsigned u0 = g_rbh[r0*512 + pc];
            unsigned u1 = g_rbh[(r0+8)*512 + pc];
            float2 b0v = __half22float2(*reinterpret_cast<__half2*>(&u0));
            float2 b1v = __half22float2(*reinterpret_cast<__half2*>(&u1));
            S_[nt][0] += b0v.x; S_[nt][1] += b0v.y;
            S_[nt][2] += b1v.x; S_[nt][3] += b1v.y;
        }

        // online softmax
        float tm0 = -1e30f, tm1 = -1e30f;
        #pragma unroll
        for (int nt = 0; nt < 8; nt++) {
            tm0 = fmaxf(tm0, fmaxf(S_[nt][0], S_[nt][1]));
            tm1 = fmaxf(tm1, fmaxf(S_[nt][2], S_[nt][3]));
        }
        tm0 = fmaxf(tm0, __shfl_xor_sync(0xffffffffu, tm0, 1));
        tm0 = fmaxf(tm0, __shfl_xor_sync(0xffffffffu, tm0, 2));
        tm1 = fmaxf(tm1, __shfl_xor_sync(0xffffffffu, tm1, 1));
        tm1 = fmaxf(tm1, __shfl_xor_sync(0xffffffffu, tm1, 2));
        float nm0 = fmaxf(m0s, tm0), nm1 = fmaxf(m1s, tm1);
        float sc0 = __expf(m0s - nm0), sc1 = __expf(m1s - nm1);
        float rs0 = 0.f, rs1 = 0.f;
        unsigned pf[8][2];
        #pragma unroll
        for (int nt = 0; nt < 8; nt++) {
            float p0 = __expf(S_[nt][0] - nm0);
            float p1 = __expf(S_[nt][1] - nm0);
            float p2 = __expf(S_[nt][2] - nm1);
            float p3 = __expf(S_[nt][3] - nm1);
            rs0 += p0 + p1;  rs1 += p2 + p3;
            pf[nt][0] = pkh(p0, p1);
            pf[nt][1] = pkh(p2, p3);
        }
        rs0 += __shfl_xor_sync(0xffffffffu, rs0, 1);
        rs0 += __shfl_xor_sync(0xffffffffu, rs0, 2);
        rs1 += __shfl_xor_sync(0xffffffffu, rs1, 1);
        rs1 += __shfl_xor_sync(0xffffffffu, rs1, 2);
        l0s = l0s*sc0 + rs0;
        l1s = l1s*sc1 + rs1;
        m0s = nm0;  m1s = nm1;
        #pragma unroll
        for (int dn = 0; dn < 4; dn++) {
            O[dn][0] *= sc0; O[dn][1] *= sc0;
            O[dn][2] *= sc1; O[dn][3] *= sc1;
        }

        // O += P @ V   (P fragments straight from registers; V via ldsm trans)
        #pragma unroll
        for (int kk = 0; kk < 4; kk++) {
            unsigned a0 = pf[2*kk][0], a1 = pf[2*kk][1];
            unsigned a2 = pf[2*kk+1][0], a3 = pf[2*kk+1][1];
            #pragma unroll
            for (int p = 0; p < 2; p++) {
                unsigned v0, v1, v2, v3;
                ldsm4t(v0, v1, v2, v3, vBase + kk*1280 + p*32);
                mmah(O[2*p  ], a0, a1, a2, a3, v0, v1);
                mmah(O[2*p+1], a0, a1, a2, a3, v2, v3);
            }
        }
        __syncthreads();
    }

    float il0 = 1.f/l0s, il1 = 1.f/l1s;
    #pragma unroll
    for (int dn = 0; dn < 4; dn++) {
        int cp = hd*16 + dn*4 + t;
        g_oph[qrow0*128 + cp] = pkh(O[dn][0]*il0, O[dn][1]*il0);
        g_oph[qrow1*128 + cp] = pkh(O[dn][2]*il1, O[dn][3]*il1);
    }
}

// ---------------- launch ----------------------------------------------------
extern "C" void kernel_launch(void* const* d_in, const int* in_sizes, int n_in,
                              void* d_out, int out_size)
{
    const float* Matrix = (const float*)d_in[0];
    const float* ln_g   = (const float*)d_in[1];
    const float* ln_b   = (const float*)d_in[2];
    const float* Wq     = (const float*)d_in[3];
    const float* bq     = (const float*)d_in[4];
    const float* Wk     = (const float*)d_in[5];
    const float* bk     = (const float*)d_in[6];
    const float* Wv     = (const float*)d_in[7];
    const float* bv     = (const float*)d_in[8];
    const float* Wo     = (const float*)d_in[9];
    const float* bo     = (const float*)d_in[10];
    const float* rel    = (const float*)d_in[11];
    const float* gW     = (const float*)d_in[12];
    const float* gb     = (const float*)d_in[13];
    const float* mW     = (const float*)d_in[14];
    const float* mb     = (const float*)d_in[15];
    float* out = (float*)d_out;

    wsplit<<<dim3(4,4,6), 256>>>(Wq, Wk, Wv, gW, Wo, mW);
    bsplit<<<SS, 256>>>(rel);
    ln_kernel<<<MROWS/8, 256>>>(Matrix, ln_g, ln_b);

    gemm_h<<<dim3(4,128,4), 256>>>(bq, bk, bv, gb, bo, mb, Matrix, 0);
    attn_h<<<dim3(BB*HH, SS/128), 256>>>();
    gemm_h<<<dim3(4,128,1), 256>>>(bq, bk, bv, gb, bo, mb, Matrix, 4);
    gemm_h<<<dim3(4,128,1), 256>>>(bq, bk, bv, gb, bo, mb, Matrix, 5);

    final_kernel<<<MROWS/8, 256>>>(ln_g, ln_b, out);
}